// round 1
// baseline (speedup 1.0000x reference)
#include <cuda_runtime.h>
#include <math.h>

#define NN 30000
#define NE 480000
#define H 128
#define NL 4
#define NGR 32
#define NOUT 12
#define AVG_LOG 1.38214548f
#define EPS_BN 1e-5f
#define EPS_STD 1e-5f

// ---------------- scratch (device globals; no allocation allowed) ----------------
__device__ float g_h[NN * H];      // current node features
__device__ float g_h2[NN * H];     // pre-BN features
__device__ float g_tmp[NN * H];    // post-NN output
__device__ float g_e[NE * H];      // embedded edge features (constant across layers)
__device__ float g_sum[NN * H];    // -> mean
__device__ float g_sq[NN * H];     // -> std
__device__ float g_mn[NN * H];
__device__ float g_mx[NN * H];
__device__ float g_deg[NN];
__device__ float g_amp[NN];
__device__ float g_iamp[NN];
__device__ float g_Wcat[384 * H];  // fused message weight per layer
__device__ float g_biasm[H];       // fused message bias
__device__ float g_bn[2 * H];
__device__ float g_pool[NGR * H];
__device__ float g_z[NGR * 64];

// ---------------- helpers ----------------
__device__ __forceinline__ void atomicMaxF(float* a, float v) {
    if (v >= 0.f) atomicMax((int*)a, __float_as_int(v));
    else          atomicMin((unsigned int*)a, __float_as_uint(v));
}
__device__ __forceinline__ void atomicMinF(float* a, float v) {
    if (v >= 0.f) atomicMin((int*)a, __float_as_int(v));
    else          atomicMax((unsigned int*)a, __float_as_uint(v));
}

// ---------------- generic tiled GEMM: C[M,128] = A[M,K] @ W[K,128] (+bias) ----------------
// BM=128, BN=128, BK=16, 256 threads, 8x8 per thread. K must be a multiple of 16.
__global__ __launch_bounds__(256) void gemm128(
    const float* __restrict__ A, const float* __restrict__ W,
    const float* __restrict__ bias, float* __restrict__ C, int M, int K)
{
    __shared__ float As[16 * 132];   // transposed: As[k][row], stride 132 (conflict mitigation)
    __shared__ float Ws[16 * 128];
    int tid = threadIdx.x;
    int m0 = blockIdx.x * 128;
    int trow = tid >> 4, tcol = tid & 15;
    int r8 = trow * 8, c8 = tcol * 8;
    int arow = tid >> 2;
    int ac4 = (tid & 3) * 4;

    float acc[8][8];
#pragma unroll
    for (int i = 0; i < 8; i++)
#pragma unroll
        for (int j = 0; j < 8; j++) acc[i][j] = 0.f;

    for (int k0 = 0; k0 < K; k0 += 16) {
#pragma unroll
        for (int t = 0; t < 2; t++) {
            int r = arow + t * 64;
            int gr = m0 + r;
            float4 v = make_float4(0.f, 0.f, 0.f, 0.f);
            if (gr < M) v = *(const float4*)(A + (size_t)gr * K + k0 + ac4);
            As[(ac4 + 0) * 132 + r] = v.x;
            As[(ac4 + 1) * 132 + r] = v.y;
            As[(ac4 + 2) * 132 + r] = v.z;
            As[(ac4 + 3) * 132 + r] = v.w;
        }
#pragma unroll
        for (int t = 0; t < 2; t++) {
            int f4i = tid + t * 256;
            int wr = f4i >> 5, wc = (f4i & 31) * 4;
            *(float4*)&Ws[wr * 128 + wc] = *(const float4*)(W + (size_t)(k0 + wr) * 128 + wc);
        }
        __syncthreads();
#pragma unroll
        for (int kk = 0; kk < 16; kk++) {
            float4 a0 = *(const float4*)&As[kk * 132 + r8];
            float4 a1 = *(const float4*)&As[kk * 132 + r8 + 4];
            float4 w0 = *(const float4*)&Ws[kk * 128 + c8];
            float4 w1 = *(const float4*)&Ws[kk * 128 + c8 + 4];
            float a[8] = {a0.x, a0.y, a0.z, a0.w, a1.x, a1.y, a1.z, a1.w};
            float w[8] = {w0.x, w0.y, w0.z, w0.w, w1.x, w1.y, w1.z, w1.w};
#pragma unroll
            for (int i = 0; i < 8; i++)
#pragma unroll
                for (int j = 0; j < 8; j++) acc[i][j] += a[i] * w[j];
        }
        __syncthreads();
    }

    float b[8];
#pragma unroll
    for (int j = 0; j < 8; j++) b[j] = bias ? bias[c8 + j] : 0.f;
#pragma unroll
    for (int i = 0; i < 8; i++) {
        int gr = m0 + r8 + i;
        if (gr < M) {
            float4 o0, o1;
            o0.x = acc[i][0] + b[0]; o0.y = acc[i][1] + b[1];
            o0.z = acc[i][2] + b[2]; o0.w = acc[i][3] + b[3];
            o1.x = acc[i][4] + b[4]; o1.y = acc[i][5] + b[5];
            o1.z = acc[i][6] + b[6]; o1.w = acc[i][7] + b[7];
            *(float4*)(C + (size_t)gr * 128 + c8) = o0;
            *(float4*)(C + (size_t)gr * 128 + c8 + 4) = o1;
        }
    }
}

// ---------------- fused edge message GEMM + aggregation ----------------
// m[e,:] = g_h[dst]@P0 + g_h[src]@P1 + g_e[e]@C + biasm ; atomically aggregate into dst.
__global__ __launch_bounds__(256) void edge_msg(const int* __restrict__ srcI,
                                                const int* __restrict__ dstI)
{
    __shared__ float As[16 * 132];
    __shared__ float Ws[16 * 128];
    __shared__ int sdst[128], ssrc[128];
    int tid = threadIdx.x;
    int e0 = blockIdx.x * 128;
    if (tid < 128) { int e = e0 + tid;        sdst[tid] = (e < NE) ? dstI[e] : 0; }
    else           { int e = e0 + tid - 128;  ssrc[tid - 128] = (e < NE) ? srcI[e] : 0; }
    __syncthreads();

    int trow = tid >> 4, tcol = tid & 15;
    int r8 = trow * 8, c8 = tcol * 8;
    int arow = tid >> 2;
    int ac4 = (tid & 3) * 4;

    float acc[8][8];
#pragma unroll
    for (int i = 0; i < 8; i++)
#pragma unroll
        for (int j = 0; j < 8; j++) acc[i][j] = 0.f;

    for (int kt = 0; kt < 24; kt++) {
        int b = kt >> 3;
        int kk0 = (kt & 7) * 16;
#pragma unroll
        for (int t = 0; t < 2; t++) {
            int r = arow + t * 64;
            int e = e0 + r;
            float4 v = make_float4(0.f, 0.f, 0.f, 0.f);
            if (e < NE) {
                const float* base;
                if (b == 0)      base = g_h + (size_t)sdst[r] * H;
                else if (b == 1) base = g_h + (size_t)ssrc[r] * H;
                else             base = g_e + (size_t)e * H;
                v = *(const float4*)(base + kk0 + ac4);
            }
            As[(ac4 + 0) * 132 + r] = v.x;
            As[(ac4 + 1) * 132 + r] = v.y;
            As[(ac4 + 2) * 132 + r] = v.z;
            As[(ac4 + 3) * 132 + r] = v.w;
        }
#pragma unroll
        for (int t = 0; t < 2; t++) {
            int f4i = tid + t * 256;
            int wr = f4i >> 5, wc = (f4i & 31) * 4;
            *(float4*)&Ws[wr * 128 + wc] =
                *(const float4*)(g_Wcat + (size_t)(kt * 16 + wr) * 128 + wc);
        }
        __syncthreads();
#pragma unroll
        for (int kk = 0; kk < 16; kk++) {
            float4 a0 = *(const float4*)&As[kk * 132 + r8];
            float4 a1 = *(const float4*)&As[kk * 132 + r8 + 4];
            float4 w0 = *(const float4*)&Ws[kk * 128 + c8];
            float4 w1 = *(const float4*)&Ws[kk * 128 + c8 + 4];
            float a[8] = {a0.x, a0.y, a0.z, a0.w, a1.x, a1.y, a1.z, a1.w};
            float w[8] = {w0.x, w0.y, w0.z, w0.w, w1.x, w1.y, w1.z, w1.w};
#pragma unroll
            for (int i = 0; i < 8; i++)
#pragma unroll
                for (int j = 0; j < 8; j++) acc[i][j] += a[i] * w[j];
        }
        __syncthreads();
    }

    float bm[8];
#pragma unroll
    for (int j = 0; j < 8; j++) bm[j] = g_biasm[c8 + j];
#pragma unroll
    for (int i = 0; i < 8; i++) {
        int r = r8 + i;
        int e = e0 + r;
        if (e < NE) {
            size_t base = (size_t)sdst[r] * H + c8;
#pragma unroll
            for (int j = 0; j < 8; j++) {
                float v = acc[i][j] + bm[j];
                atomicAdd(&g_sum[base + j], v);
                atomicAdd(&g_sq[base + j], v * v);
                atomicMaxF(&g_mx[base + j], v);
                atomicMinF(&g_mn[base + j], v);
            }
        }
    }
}

// ---------------- post-NN: virtual [N, 13H] gather-GEMM ----------------
__global__ __launch_bounds__(256) void post_gemm(const float* __restrict__ W,
                                                 const float* __restrict__ bias)
{
    __shared__ float As[16 * 132];
    __shared__ float Ws[16 * 128];
    __shared__ float samp[128], siamp[128];
    int tid = threadIdx.x;
    int n0 = blockIdx.x * 128;
    if (tid < 128)      { int n = n0 + tid;        samp[tid] = (n < NN) ? g_amp[n] : 1.f; }
    else                { int n = n0 + tid - 128;  siamp[tid - 128] = (n < NN) ? g_iamp[n] : 1.f; }
    __syncthreads();

    int trow = tid >> 4, tcol = tid & 15;
    int r8 = trow * 8, c8 = tcol * 8;
    int arow = tid >> 2;
    int ac4 = (tid & 3) * 4;

    float acc[8][8];
#pragma unroll
    for (int i = 0; i < 8; i++)
#pragma unroll
        for (int j = 0; j < 8; j++) acc[i][j] = 0.f;

    for (int kt = 0; kt < 104; kt++) {
        int b = kt >> 3;           // 0..12
        int kk0 = (kt & 7) * 16;
        const float* src;
        if (b == 0) src = g_h;
        else {
            int a = (b - 1) & 3;   // 0 mean, 1 min, 2 max, 3 std
            src = (a == 0) ? g_sum : (a == 1) ? g_mn : (a == 2) ? g_mx : g_sq;
        }
#pragma unroll
        for (int t = 0; t < 2; t++) {
            int r = arow + t * 64;
            int n = n0 + r;
            float4 v = make_float4(0.f, 0.f, 0.f, 0.f);
            if (n < NN) {
                v = *(const float4*)(src + (size_t)n * H + kk0 + ac4);
                float s = (b <= 4) ? 1.f : (b <= 8) ? samp[r] : siamp[r];
                v.x *= s; v.y *= s; v.z *= s; v.w *= s;
            }
            As[(ac4 + 0) * 132 + r] = v.x;
            As[(ac4 + 1) * 132 + r] = v.y;
            As[(ac4 + 2) * 132 + r] = v.z;
            As[(ac4 + 3) * 132 + r] = v.w;
        }
#pragma unroll
        for (int t = 0; t < 2; t++) {
            int f4i = tid + t * 256;
            int wr = f4i >> 5, wc = (f4i & 31) * 4;
            *(float4*)&Ws[wr * 128 + wc] =
                *(const float4*)(W + (size_t)(kt * 16 + wr) * 128 + wc);
        }
        __syncthreads();
#pragma unroll
        for (int kk = 0; kk < 16; kk++) {
            float4 a0 = *(const float4*)&As[kk * 132 + r8];
            float4 a1 = *(const float4*)&As[kk * 132 + r8 + 4];
            float4 w0 = *(const float4*)&Ws[kk * 128 + c8];
            float4 w1 = *(const float4*)&Ws[kk * 128 + c8 + 4];
            float a[8] = {a0.x, a0.y, a0.z, a0.w, a1.x, a1.y, a1.z, a1.w};
            float w[8] = {w0.x, w0.y, w0.z, w0.w, w1.x, w1.y, w1.z, w1.w};
#pragma unroll
            for (int i = 0; i < 8; i++)
#pragma unroll
                for (int j = 0; j < 8; j++) acc[i][j] += a[i] * w[j];
        }
        __syncthreads();
    }

    float b8[8];
#pragma unroll
    for (int j = 0; j < 8; j++) b8[j] = bias[c8 + j];
#pragma unroll
    for (int i = 0; i < 8; i++) {
        int n = n0 + r8 + i;
        if (n < NN) {
            float4 o0, o1;
            o0.x = acc[i][0] + b8[0]; o0.y = acc[i][1] + b8[1];
            o0.z = acc[i][2] + b8[2]; o0.w = acc[i][3] + b8[3];
            o1.x = acc[i][4] + b8[4]; o1.y = acc[i][5] + b8[5];
            o1.z = acc[i][6] + b8[6]; o1.w = acc[i][7] + b8[7];
            *(float4*)(g_tmp + (size_t)n * 128 + c8) = o0;
            *(float4*)(g_tmp + (size_t)n * 128 + c8 + 4) = o1;
        }
    }
}

// ---------------- small kernels ----------------
__global__ void init_agg() {
    int idx = blockIdx.x * blockDim.x + threadIdx.x;
    if (idx < NN * H) {
        g_sum[idx] = 0.f; g_sq[idx] = 0.f;
        g_mn[idx] = INFINITY; g_mx[idx] = -INFINITY;
    }
}
__global__ void init_deg() {
    int idx = blockIdx.x * blockDim.x + threadIdx.x;
    if (idx < NN) g_deg[idx] = 0.f;
}
__global__ void deg_count(const int* __restrict__ dstI) {
    int e = blockIdx.x * blockDim.x + threadIdx.x;
    if (e < NE) atomicAdd(&g_deg[dstI[e]], 1.f);
}
__global__ void copy_wcat(const float* __restrict__ preW) {
    int idx = blockIdx.x * blockDim.x + threadIdx.x;
    if (idx < 256 * H) g_Wcat[idx] = preW[idx];
}
__global__ void biasm_k(const float* __restrict__ eb, const float* __restrict__ W2,
                        const float* __restrict__ pb) {
    int j = threadIdx.x;
    float s = pb[j];
    for (int k = 0; k < H; k++) s += eb[k] * W2[k * H + j];
    g_biasm[j] = s;
}
__global__ void finalize_k() {
    int idx = blockIdx.x * blockDim.x + threadIdx.x;
    if (idx >= NN * H) return;
    int n = idx >> 7;
    float deg = g_deg[n];
    float degc = fmaxf(deg, 1.f);
    bool has = deg > 0.f;
    float inv = 1.f / degc;
    float mean = g_sum[idx] * inv;
    float msq = g_sq[idx] * inv;
    float var = fmaxf(msq - mean * mean, 0.f);
    g_sum[idx] = mean;
    g_sq[idx] = sqrtf(var + EPS_STD);
    g_mn[idx] = has ? g_mn[idx] : 0.f;
    g_mx[idx] = has ? g_mx[idx] : 0.f;
}
__global__ void amp_k() {
    int n = blockIdx.x * blockDim.x + threadIdx.x;
    if (n >= NN) return;
    float degc = fmaxf(g_deg[n], 1.f);
    float a = logf(degc + 1.f) / AVG_LOG;
    g_amp[n] = a;
    g_iamp[n] = 1.f / a;
}
__global__ void bn_zero() { g_bn[threadIdx.x] = 0.f; }
__global__ void bn_stats() {
    int tid = threadIdx.x;
    int half = tid >> 7;
    float s = 0.f, q = 0.f;
    for (int row = blockIdx.x * 2 + half; row < NN; row += gridDim.x * 2) {
        float v = g_h2[(size_t)row * H + (tid & 127)];
        s += v; q += v * v;
    }
    __shared__ float sh[256];
    sh[tid] = s; __syncthreads();
    if (tid < 128) atomicAdd(&g_bn[tid], sh[tid] + sh[tid + 128]);
    __syncthreads();
    sh[tid] = q; __syncthreads();
    if (tid < 128) atomicAdd(&g_bn[128 + tid], sh[tid] + sh[tid + 128]);
}
__global__ void bn_norm(const float* __restrict__ gamma, const float* __restrict__ beta) {
    int idx = blockIdx.x * blockDim.x + threadIdx.x;
    if (idx >= NN * H) return;
    int c = idx & 127;
    const float invN = 1.f / (float)NN;
    float mu = g_bn[c] * invN;
    float var = g_bn[128 + c] * invN - mu * mu;
    float y = (g_h2[idx] - mu) * rsqrtf(var + EPS_BN) * gamma[c] + beta[c];
    g_h[idx] = fmaxf(y, 0.f);
}
__global__ void init_pool() {
    int idx = blockIdx.x * blockDim.x + threadIdx.x;
    if (idx < NGR * H) g_pool[idx] = 0.f;
}
__global__ void pool_k(const int* __restrict__ batch) {
    int c = threadIdx.x;  // 128 threads = channels
    int start = blockIdx.x * 256;
    int end = min(start + 256, NN);
    if (start >= NN) return;
    float acc = 0.f;
    int cur = batch[start];
    for (int n = start; n < end; n++) {
        int g = batch[n];
        if (g != cur) { atomicAdd(&g_pool[cur * H + c], acc); acc = 0.f; cur = g; }
        acc += g_h[(size_t)n * H + c];
    }
    atomicAdd(&g_pool[cur * H + c], acc);
}
__global__ void head1_k(const float* __restrict__ W1, const float* __restrict__ b1) {
    int idx = blockIdx.x * blockDim.x + threadIdx.x;
    if (idx >= NGR * 64) return;
    int g = idx >> 6, j = idx & 63;
    float s = b1[j];
    for (int k = 0; k < H; k++) s += g_pool[g * H + k] * W1[k * 64 + j];
    g_z[idx] = fmaxf(s, 0.f);
}
__global__ void head2_k(const float* __restrict__ W2, const float* __restrict__ b2,
                        float* __restrict__ out) {
    int idx = blockIdx.x * blockDim.x + threadIdx.x;
    if (idx >= NGR * NOUT) return;
    int g = idx / NOUT, j = idx % NOUT;
    float s = b2[j];
    for (int k = 0; k < 64; k++) s += g_z[g * 64 + k] * W2[k * NOUT + j];
    out[idx] = s;
}

// ---------------- launch ----------------
extern "C" void kernel_launch(void* const* d_in, const int* in_sizes, int n_in,
                              void* d_out, int out_size)
{
    // Input-order detection: signature order (x, edge_index, batch, edge_attr, ...)
    // vs setup-dict order (x, edge_attr, edge_index, batch, ...).
    int iEI = 1, iBatch = 2, iEA = 3;
    if (in_sizes[1] == NE * 16) { iEA = 1; iEI = 2; iBatch = 3; }

    const float* x         = (const float*)d_in[0];
    const int*   edge_index= (const int*)  d_in[iEI];
    const int*   batch     = (const int*)  d_in[iBatch];
    const float* edge_attr = (const float*)d_in[iEA];
    const float* node_emb_W= (const float*)d_in[4];
    const float* node_emb_b= (const float*)d_in[5];
    const float* edge_emb_W= (const float*)d_in[6];
    const float* edge_emb_b= (const float*)d_in[7];
    const float* edge_enc_W= (const float*)d_in[8];
    const float* edge_enc_b= (const float*)d_in[9];
    const float* pre_W     = (const float*)d_in[10];
    const float* pre_b     = (const float*)d_in[11];
    const float* post_W    = (const float*)d_in[12];
    const float* post_b    = (const float*)d_in[13];
    const float* lin_W     = (const float*)d_in[14];
    const float* lin_b     = (const float*)d_in[15];
    const float* bn_gamma  = (const float*)d_in[16];
    const float* bn_beta   = (const float*)d_in[17];
    const float* head1_W   = (const float*)d_in[18];
    const float* head1_b   = (const float*)d_in[19];
    const float* head2_W   = (const float*)d_in[20];
    const float* head2_b   = (const float*)d_in[21];

    const int* srcI = edge_index;       // row 0
    const int* dstI = edge_index + NE;  // row 1

    float *p_h, *p_h2, *p_tmp, *p_e, *p_wcat;
    cudaGetSymbolAddress((void**)&p_h,    g_h);
    cudaGetSymbolAddress((void**)&p_h2,   g_h2);
    cudaGetSymbolAddress((void**)&p_tmp,  g_tmp);
    cudaGetSymbolAddress((void**)&p_e,    g_e);
    cudaGetSymbolAddress((void**)&p_wcat, g_Wcat);

    // Embeddings
    gemm128<<<(NN + 127) / 128, 256>>>(x, node_emb_W, node_emb_b, p_h, NN, 64);
    gemm128<<<(NE + 127) / 128, 256>>>(edge_attr, edge_emb_W, edge_emb_b, p_e, NE, 16);

    // Degrees (dst fixed across layers)
    init_deg<<<(NN + 255) / 256, 256>>>();
    deg_count<<<(NE + 255) / 256, 256>>>(dstI);
    amp_k<<<(NN + 255) / 256, 256>>>();

    for (int l = 0; l < NL; l++) {
        const float* preWl = pre_W + (size_t)l * 384 * H;
        // Fused message weight: rows [0:256) = preW (dst,src parts); rows [256:384) = eW @ preW2
        copy_wcat<<<128, 256>>>(preWl);
        gemm128<<<1, 256>>>(edge_enc_W + (size_t)l * H * H, preWl + 256 * H,
                            (const float*)nullptr, p_wcat + 256 * H, 128, 128);
        biasm_k<<<1, 128>>>(edge_enc_b + l * H, preWl + 256 * H, pre_b + l * H);

        init_agg<<<(NN * H + 255) / 256, 256>>>();
        edge_msg<<<NE / 128, 256>>>(srcI, dstI);
        finalize_k<<<(NN * H + 255) / 256, 256>>>();

        post_gemm<<<(NN + 127) / 128, 256>>>(post_W + (size_t)l * 13 * H * H, post_b + l * H);
        gemm128<<<(NN + 127) / 128, 256>>>(p_tmp, lin_W + (size_t)l * H * H,
                                           lin_b + l * H, p_h2, NN, H);

        bn_zero<<<1, 256>>>();
        bn_stats<<<128, 256>>>();
        bn_norm<<<(NN * H + 255) / 256, 256>>>(bn_gamma + l * H, bn_beta + l * H);
    }

    // Pool + head
    init_pool<<<16, 256>>>();
    pool_k<<<(NN + 255) / 256, 128>>>(batch);
    head1_k<<<8, 256>>>(head1_W, head1_b);
    head2_k<<<2, 256>>>(head2_W, head2_b, (float*)d_out);
}

// round 2
// speedup vs baseline: 1.7530x; 1.7530x over previous
#include <cuda_runtime.h>
#include <math.h>

#define NN 30000
#define NE 480000
#define H 128
#define NL 4
#define NGR 32
#define NOUT 12
#define AVG_LOG 1.38214548f
#define EPS_BN 1e-5f
#define EPS_STD 1e-5f
#define KCAT 272   // 128 dst + 128 src + 16 edge_attr
#define KT_N 17    // KCAT / 16

// ---------------- scratch ----------------
__device__ float g_h[NN * H];
__device__ float g_h2[NN * H];
__device__ float g_tmp[NN * H];
__device__ float g_m[NE * H];        // permuted edge messages
__device__ float g_mean[NN * H];
__device__ float g_std[NN * H];
__device__ float g_mn[NN * H];
__device__ float g_mx[NN * H];
__device__ int   g_cnt[NN];
__device__ int   g_start[NN + 1];
__device__ int   g_cursor[NN];
__device__ int   g_psrc[NE];
__device__ int   g_pdst[NE];
__device__ int   g_peid[NE];
__device__ float g_amp[NN];
__device__ float g_iamp[NN];
__device__ float g_Wcat[KCAT * H];
__device__ float g_T1[H * H];
__device__ float g_biasm[H];
__device__ float g_bn[2 * H];
__device__ float g_pool[NGR * H];
__device__ float g_z[NGR * 64];

// ---------------- generic tiled GEMM: C[M,128] = A[M,K] @ W[K,128] (+bias) ----------------
__global__ __launch_bounds__(256) void gemm128(
    const float* __restrict__ A, const float* __restrict__ W,
    const float* __restrict__ bias, float* __restrict__ C, int M, int K)
{
    __shared__ float As[16 * 132];
    __shared__ float Ws[16 * 128];
    int tid = threadIdx.x;
    int m0 = blockIdx.x * 128;
    int trow = tid >> 4, tcol = tid & 15;
    int r8 = trow * 8, c8 = tcol * 8;
    int arow = tid >> 2;
    int ac4 = (tid & 3) * 4;

    float acc[8][8];
#pragma unroll
    for (int i = 0; i < 8; i++)
#pragma unroll
        for (int j = 0; j < 8; j++) acc[i][j] = 0.f;

    for (int k0 = 0; k0 < K; k0 += 16) {
#pragma unroll
        for (int t = 0; t < 2; t++) {
            int r = arow + t * 64;
            int gr = m0 + r;
            float4 v = make_float4(0.f, 0.f, 0.f, 0.f);
            if (gr < M) v = *(const float4*)(A + (size_t)gr * K + k0 + ac4);
            As[(ac4 + 0) * 132 + r] = v.x;
            As[(ac4 + 1) * 132 + r] = v.y;
            As[(ac4 + 2) * 132 + r] = v.z;
            As[(ac4 + 3) * 132 + r] = v.w;
        }
#pragma unroll
        for (int t = 0; t < 2; t++) {
            int f4i = tid + t * 256;
            int wr = f4i >> 5, wc = (f4i & 31) * 4;
            *(float4*)&Ws[wr * 128 + wc] = *(const float4*)(W + (size_t)(k0 + wr) * 128 + wc);
        }
        __syncthreads();
#pragma unroll
        for (int kk = 0; kk < 16; kk++) {
            float4 a0 = *(const float4*)&As[kk * 132 + r8];
            float4 a1 = *(const float4*)&As[kk * 132 + r8 + 4];
            float4 w0 = *(const float4*)&Ws[kk * 128 + c8];
            float4 w1 = *(const float4*)&Ws[kk * 128 + c8 + 4];
            float a[8] = {a0.x, a0.y, a0.z, a0.w, a1.x, a1.y, a1.z, a1.w};
            float w[8] = {w0.x, w0.y, w0.z, w0.w, w1.x, w1.y, w1.z, w1.w};
#pragma unroll
            for (int i = 0; i < 8; i++)
#pragma unroll
                for (int j = 0; j < 8; j++) acc[i][j] += a[i] * w[j];
        }
        __syncthreads();
    }

    float b[8];
#pragma unroll
    for (int j = 0; j < 8; j++) b[j] = bias ? bias[c8 + j] : 0.f;
#pragma unroll
    for (int i = 0; i < 8; i++) {
        int gr = m0 + r8 + i;
        if (gr < M) {
            float4 o0, o1;
            o0.x = acc[i][0] + b[0]; o0.y = acc[i][1] + b[1];
            o0.z = acc[i][2] + b[2]; o0.w = acc[i][3] + b[3];
            o1.x = acc[i][4] + b[4]; o1.y = acc[i][5] + b[5];
            o1.z = acc[i][6] + b[6]; o1.w = acc[i][7] + b[7];
            *(float4*)(C + (size_t)gr * 128 + c8) = o0;
            *(float4*)(C + (size_t)gr * 128 + c8 + 4) = o1;
        }
    }
}

// ---------------- edge message GEMM over sorted edges; coalesced store ----------------
__global__ __launch_bounds__(256) void edge_msg(const float* __restrict__ edge_attr)
{
    __shared__ float As[16 * 132];
    __shared__ float Ws[16 * 128];
    __shared__ int sdst[128], ssrc[128], seid[128];
    int tid = threadIdx.x;
    int e0 = blockIdx.x * 128;
    if (tid < 128) {
        int p = e0 + tid;
        sdst[tid] = g_pdst[p];
        ssrc[tid] = g_psrc[p];
        seid[tid] = g_peid[p];
    }
    __syncthreads();

    int trow = tid >> 4, tcol = tid & 15;
    int r8 = trow * 8, c8 = tcol * 8;
    int arow = tid >> 2;
    int ac4 = (tid & 3) * 4;

    float acc[8][8];
#pragma unroll
    for (int i = 0; i < 8; i++)
#pragma unroll
        for (int j = 0; j < 8; j++) acc[i][j] = 0.f;

    for (int kt = 0; kt < KT_N; kt++) {
#pragma unroll
        for (int t = 0; t < 2; t++) {
            int r = arow + t * 64;
            float4 v;
            if (kt < 8)
                v = *(const float4*)(g_h + (size_t)sdst[r] * H + kt * 16 + ac4);
            else if (kt < 16)
                v = *(const float4*)(g_h + (size_t)ssrc[r] * H + (kt - 8) * 16 + ac4);
            else
                v = *(const float4*)(edge_attr + (size_t)seid[r] * 16 + ac4);
            As[(ac4 + 0) * 132 + r] = v.x;
            As[(ac4 + 1) * 132 + r] = v.y;
            As[(ac4 + 2) * 132 + r] = v.z;
            As[(ac4 + 3) * 132 + r] = v.w;
        }
#pragma unroll
        for (int t = 0; t < 2; t++) {
            int f4i = tid + t * 256;
            int wr = f4i >> 5, wc = (f4i & 31) * 4;
            *(float4*)&Ws[wr * 128 + wc] =
                *(const float4*)(g_Wcat + (size_t)(kt * 16 + wr) * 128 + wc);
        }
        __syncthreads();
#pragma unroll
        for (int kk = 0; kk < 16; kk++) {
            float4 a0 = *(const float4*)&As[kk * 132 + r8];
            float4 a1 = *(const float4*)&As[kk * 132 + r8 + 4];
            float4 w0 = *(const float4*)&Ws[kk * 128 + c8];
            float4 w1 = *(const float4*)&Ws[kk * 128 + c8 + 4];
            float a[8] = {a0.x, a0.y, a0.z, a0.w, a1.x, a1.y, a1.z, a1.w};
            float w[8] = {w0.x, w0.y, w0.z, w0.w, w1.x, w1.y, w1.z, w1.w};
#pragma unroll
            for (int i = 0; i < 8; i++)
#pragma unroll
                for (int j = 0; j < 8; j++) acc[i][j] += a[i] * w[j];
        }
        __syncthreads();
    }

    float bm[8];
#pragma unroll
    for (int j = 0; j < 8; j++) bm[j] = g_biasm[c8 + j];
#pragma unroll
    for (int i = 0; i < 8; i++) {
        int p = e0 + r8 + i;
        float4 o0, o1;
        o0.x = acc[i][0] + bm[0]; o0.y = acc[i][1] + bm[1];
        o0.z = acc[i][2] + bm[2]; o0.w = acc[i][3] + bm[3];
        o1.x = acc[i][4] + bm[4]; o1.y = acc[i][5] + bm[5];
        o1.z = acc[i][6] + bm[6]; o1.w = acc[i][7] + bm[7];
        *(float4*)(g_m + (size_t)p * 128 + c8) = o0;
        *(float4*)(g_m + (size_t)p * 128 + c8 + 4) = o1;
    }
}

// ---------------- node-centric segmented aggregation (atomic-free) ----------------
__global__ __launch_bounds__(128) void agg_k()
{
    int n = blockIdx.x;
    int c = threadIdx.x;
    int start = g_start[n];
    int cnt = g_start[n + 1] - start;
    float s = 0.f, q = 0.f, mn = INFINITY, mx = -INFINITY;
    for (int i = 0; i < cnt; i++) {
        float v = g_m[(size_t)(start + i) * 128 + c];
        s += v; q += v * v;
        mn = fminf(mn, v); mx = fmaxf(mx, v);
    }
    float degc = fmaxf((float)cnt, 1.f);
    float inv = 1.f / degc;
    float mean = s * inv;
    float var = fmaxf(q * inv - mean * mean, 0.f);
    size_t idx = (size_t)n * 128 + c;
    g_mean[idx] = mean;
    g_std[idx] = sqrtf(var + EPS_STD);
    g_mn[idx] = (cnt > 0) ? mn : 0.f;
    g_mx[idx] = (cnt > 0) ? mx : 0.f;
}

// ---------------- post-NN: virtual [N, 13H] gather-GEMM ----------------
__global__ __launch_bounds__(256) void post_gemm(const float* __restrict__ W,
                                                 const float* __restrict__ bias)
{
    __shared__ float As[16 * 132];
    __shared__ float Ws[16 * 128];
    __shared__ float samp[128], siamp[128];
    int tid = threadIdx.x;
    int n0 = blockIdx.x * 128;
    if (tid < 128)      { int n = n0 + tid;        samp[tid] = (n < NN) ? g_amp[n] : 1.f; }
    else                { int n = n0 + tid - 128;  siamp[tid - 128] = (n < NN) ? g_iamp[n] : 1.f; }
    __syncthreads();

    int trow = tid >> 4, tcol = tid & 15;
    int r8 = trow * 8, c8 = tcol * 8;
    int arow = tid >> 2;
    int ac4 = (tid & 3) * 4;

    float acc[8][8];
#pragma unroll
    for (int i = 0; i < 8; i++)
#pragma unroll
        for (int j = 0; j < 8; j++) acc[i][j] = 0.f;

    for (int kt = 0; kt < 104; kt++) {
        int b = kt >> 3;
        int kk0 = (kt & 7) * 16;
        const float* src;
        if (b == 0) src = g_h;
        else {
            int a = (b - 1) & 3;
            src = (a == 0) ? g_mean : (a == 1) ? g_mn : (a == 2) ? g_mx : g_std;
        }
#pragma unroll
        for (int t = 0; t < 2; t++) {
            int r = arow + t * 64;
            int n = n0 + r;
            float4 v = make_float4(0.f, 0.f, 0.f, 0.f);
            if (n < NN) {
                v = *(const float4*)(src + (size_t)n * H + kk0 + ac4);
                float s = (b <= 4) ? 1.f : (b <= 8) ? samp[r] : siamp[r];
                v.x *= s; v.y *= s; v.z *= s; v.w *= s;
            }
            As[(ac4 + 0) * 132 + r] = v.x;
            As[(ac4 + 1) * 132 + r] = v.y;
            As[(ac4 + 2) * 132 + r] = v.z;
            As[(ac4 + 3) * 132 + r] = v.w;
        }
#pragma unroll
        for (int t = 0; t < 2; t++) {
            int f4i = tid + t * 256;
            int wr = f4i >> 5, wc = (f4i & 31) * 4;
            *(float4*)&Ws[wr * 128 + wc] =
                *(const float4*)(W + (size_t)(kt * 16 + wr) * 128 + wc);
        }
        __syncthreads();
#pragma unroll
        for (int kk = 0; kk < 16; kk++) {
            float4 a0 = *(const float4*)&As[kk * 132 + r8];
            float4 a1 = *(const float4*)&As[kk * 132 + r8 + 4];
            float4 w0 = *(const float4*)&Ws[kk * 128 + c8];
            float4 w1 = *(const float4*)&Ws[kk * 128 + c8 + 4];
            float a[8] = {a0.x, a0.y, a0.z, a0.w, a1.x, a1.y, a1.z, a1.w};
            float w[8] = {w0.x, w0.y, w0.z, w0.w, w1.x, w1.y, w1.z, w1.w};
#pragma unroll
            for (int i = 0; i < 8; i++)
#pragma unroll
                for (int j = 0; j < 8; j++) acc[i][j] += a[i] * w[j];
        }
        __syncthreads();
    }

    float b8[8];
#pragma unroll
    for (int j = 0; j < 8; j++) b8[j] = bias[c8 + j];
#pragma unroll
    for (int i = 0; i < 8; i++) {
        int n = n0 + r8 + i;
        if (n < NN) {
            float4 o0, o1;
            o0.x = acc[i][0] + b8[0]; o0.y = acc[i][1] + b8[1];
            o0.z = acc[i][2] + b8[2]; o0.w = acc[i][3] + b8[3];
            o1.x = acc[i][4] + b8[4]; o1.y = acc[i][5] + b8[5];
            o1.z = acc[i][6] + b8[6]; o1.w = acc[i][7] + b8[7];
            *(float4*)(g_tmp + (size_t)n * 128 + c8) = o0;
            *(float4*)(g_tmp + (size_t)n * 128 + c8 + 4) = o1;
        }
    }
}

// ---------------- sorting + small kernels ----------------
__global__ void init_cnt() {
    int idx = blockIdx.x * blockDim.x + threadIdx.x;
    if (idx < NN) g_cnt[idx] = 0;
}
__global__ void deg_count(const int* __restrict__ dstI) {
    int e = blockIdx.x * blockDim.x + threadIdx.x;
    if (e < NE) atomicAdd(&g_cnt[dstI[e]], 1);
}
__global__ __launch_bounds__(1024) void scan_k() {
    __shared__ int sh[1024];
    int t = threadIdx.x;
    int base = t * 30;
    int s = 0;
    for (int i = 0; i < 30; i++) {
        int n = base + i;
        if (n < NN) s += g_cnt[n];
    }
    sh[t] = s; __syncthreads();
    for (int off = 1; off < 1024; off <<= 1) {
        int v = (t >= off) ? sh[t - off] : 0;
        __syncthreads();
        sh[t] += v;
        __syncthreads();
    }
    int run = (t == 0) ? 0 : sh[t - 1];
    for (int i = 0; i < 30; i++) {
        int n = base + i;
        if (n < NN) { g_start[n] = run; g_cursor[n] = run; run += g_cnt[n]; }
    }
    if (t == 1023) g_start[NN] = run;
}
__global__ void scatter_k(const int* __restrict__ srcI, const int* __restrict__ dstI) {
    int e = blockIdx.x * blockDim.x + threadIdx.x;
    if (e >= NE) return;
    int d = dstI[e];
    int p = atomicAdd(&g_cursor[d], 1);
    g_psrc[p] = srcI[e];
    g_pdst[p] = d;
    g_peid[p] = e;
}
__global__ void copy_wcat(const float* __restrict__ preW) {
    int idx = blockIdx.x * blockDim.x + threadIdx.x;
    if (idx < 256 * H) g_Wcat[idx] = preW[idx];
}
__global__ void biasm_k(const float* __restrict__ be, const float* __restrict__ eb,
                        const float* __restrict__ P2, const float* __restrict__ pb) {
    int j = threadIdx.x;
    float s = pb[j];
    for (int k = 0; k < 16; k++)  s += be[k] * g_T1[k * H + j];
    for (int k = 0; k < H; k++)   s += eb[k] * P2[k * H + j];
    g_biasm[j] = s;
}
__global__ void amp_k() {
    int n = blockIdx.x * blockDim.x + threadIdx.x;
    if (n >= NN) return;
    float degc = fmaxf((float)g_cnt[n], 1.f);
    float a = logf(degc + 1.f) / AVG_LOG;
    g_amp[n] = a;
    g_iamp[n] = 1.f / a;
}
__global__ void bn_zero() { g_bn[threadIdx.x] = 0.f; }
__global__ void bn_stats() {
    int tid = threadIdx.x;
    int half = tid >> 7;
    float s = 0.f, q = 0.f;
    for (int row = blockIdx.x * 2 + half; row < NN; row += gridDim.x * 2) {
        float v = g_h2[(size_t)row * H + (tid & 127)];
        s += v; q += v * v;
    }
    __shared__ float sh[256];
    sh[tid] = s; __syncthreads();
    if (tid < 128) atomicAdd(&g_bn[tid], sh[tid] + sh[tid + 128]);
    __syncthreads();
    sh[tid] = q; __syncthreads();
    if (tid < 128) atomicAdd(&g_bn[128 + tid], sh[tid] + sh[tid + 128]);
}
__global__ void bn_norm(const float* __restrict__ gamma, const float* __restrict__ beta) {
    int idx = blockIdx.x * blockDim.x + threadIdx.x;
    if (idx >= NN * H) return;
    int c = idx & 127;
    const float invN = 1.f / (float)NN;
    float mu = g_bn[c] * invN;
    float var = g_bn[128 + c] * invN - mu * mu;
    float y = (g_h2[idx] - mu) * rsqrtf(var + EPS_BN) * gamma[c] + beta[c];
    g_h[idx] = fmaxf(y, 0.f);
}
__global__ void init_pool() {
    int idx = blockIdx.x * blockDim.x + threadIdx.x;
    if (idx < NGR * H) g_pool[idx] = 0.f;
}
__global__ void pool_k(const int* __restrict__ batch) {
    int c = threadIdx.x;
    int start = blockIdx.x * 256;
    int end = min(start + 256, NN);
    if (start >= NN) return;
    float acc = 0.f;
    int cur = batch[start];
    for (int n = start; n < end; n++) {
        int g = batch[n];
        if (g != cur) { atomicAdd(&g_pool[cur * H + c], acc); acc = 0.f; cur = g; }
        acc += g_h[(size_t)n * H + c];
    }
    atomicAdd(&g_pool[cur * H + c], acc);
}
__global__ void head1_k(const float* __restrict__ W1, const float* __restrict__ b1) {
    int idx = blockIdx.x * blockDim.x + threadIdx.x;
    if (idx >= NGR * 64) return;
    int g = idx >> 6, j = idx & 63;
    float s = b1[j];
    for (int k = 0; k < H; k++) s += g_pool[g * H + k] * W1[k * 64 + j];
    g_z[idx] = fmaxf(s, 0.f);
}
__global__ void head2_k(const float* __restrict__ W2, const float* __restrict__ b2,
                        float* __restrict__ out) {
    int idx = blockIdx.x * blockDim.x + threadIdx.x;
    if (idx >= NGR * NOUT) return;
    int g = idx / NOUT, j = idx % NOUT;
    float s = b2[j];
    for (int k = 0; k < 64; k++) s += g_z[g * 64 + k] * W2[k * NOUT + j];
    out[idx] = s;
}

// ---------------- launch ----------------
extern "C" void kernel_launch(void* const* d_in, const int* in_sizes, int n_in,
                              void* d_out, int out_size)
{
    int iEI = 1, iBatch = 2, iEA = 3;
    if (in_sizes[1] == NE * 16) { iEA = 1; iEI = 2; iBatch = 3; }

    const float* x         = (const float*)d_in[0];
    const int*   edge_index= (const int*)  d_in[iEI];
    const int*   batch     = (const int*)  d_in[iBatch];
    const float* edge_attr = (const float*)d_in[iEA];
    const float* node_emb_W= (const float*)d_in[4];
    const float* node_emb_b= (const float*)d_in[5];
    const float* edge_emb_W= (const float*)d_in[6];
    const float* edge_emb_b= (const float*)d_in[7];
    const float* edge_enc_W= (const float*)d_in[8];
    const float* edge_enc_b= (const float*)d_in[9];
    const float* pre_W     = (const float*)d_in[10];
    const float* pre_b     = (const float*)d_in[11];
    const float* post_W    = (const float*)d_in[12];
    const float* post_b    = (const float*)d_in[13];
    const float* lin_W     = (const float*)d_in[14];
    const float* lin_b     = (const float*)d_in[15];
    const float* bn_gamma  = (const float*)d_in[16];
    const float* bn_beta   = (const float*)d_in[17];
    const float* head1_W   = (const float*)d_in[18];
    const float* head1_b   = (const float*)d_in[19];
    const float* head2_W   = (const float*)d_in[20];
    const float* head2_b   = (const float*)d_in[21];

    const int* srcI = edge_index;
    const int* dstI = edge_index + NE;

    float *p_h, *p_h2, *p_tmp, *p_wcat, *p_T1;
    cudaGetSymbolAddress((void**)&p_h,    g_h);
    cudaGetSymbolAddress((void**)&p_h2,   g_h2);
    cudaGetSymbolAddress((void**)&p_tmp,  g_tmp);
    cudaGetSymbolAddress((void**)&p_wcat, g_Wcat);
    cudaGetSymbolAddress((void**)&p_T1,   g_T1);

    // Node embedding
    gemm128<<<(NN + 127) / 128, 256>>>(x, node_emb_W, node_emb_b, p_h, NN, 64);

    // Sort edges by dst (dst fixed across layers)
    init_cnt<<<(NN + 255) / 256, 256>>>();
    deg_count<<<(NE + 255) / 256, 256>>>(dstI);
    scan_k<<<1, 1024>>>();
    scatter_k<<<(NE + 255) / 256, 256>>>(srcI, dstI);
    amp_k<<<(NN + 255) / 256, 256>>>();

    for (int l = 0; l < NL; l++) {
        const float* preWl = pre_W + (size_t)l * 384 * H;
        const float* P2 = preWl + 256 * H;
        // Fused message weight [272,128]: rows 0:256 = preW(dst,src); rows 256:272 = We@(eW@P2)
        copy_wcat<<<128, 256>>>(preWl);
        gemm128<<<1, 256>>>(edge_enc_W + (size_t)l * H * H, P2,
                            (const float*)nullptr, p_T1, 128, 128);
        gemm128<<<1, 256>>>(edge_emb_W, p_T1,
                            (const float*)nullptr, p_wcat + 256 * H, 16, 128);
        biasm_k<<<1, 128>>>(edge_emb_b, edge_enc_b + l * H, P2, pre_b + l * H);

        edge_msg<<<NE / 128, 256>>>(edge_attr);
        agg_k<<<NN, 128>>>();

        post_gemm<<<(NN + 127) / 128, 256>>>(post_W + (size_t)l * 13 * H * H, post_b + l * H);
        gemm128<<<(NN + 127) / 128, 256>>>(p_tmp, lin_W + (size_t)l * H * H,
                                           lin_b + l * H, p_h2, NN, H);

        bn_zero<<<1, 256>>>();
        bn_stats<<<128, 256>>>();
        bn_norm<<<(NN * H + 255) / 256, 256>>>(bn_gamma + l * H, bn_beta + l * H);
    }

    init_pool<<<16, 256>>>();
    pool_k<<<(NN + 255) / 256, 128>>>(batch);
    head1_k<<<8, 256>>>(head1_W, head1_b);
    head2_k<<<2, 256>>>(head2_W, head2_b, (float*)d_out);
}

// round 3
// speedup vs baseline: 3.5456x; 2.0226x over previous
#include <cuda_runtime.h>
#include <math.h>

#define NN 30000
#define NE 480000
#define H 128
#define NL 4
#define NGR 32
#define NOUT 12
#define AVG_LOG 1.38214548f
#define EPS_BN 1e-5f
#define EPS_STD 1e-5f
#define KCAT 272
#define WS_STRIDE 136

// ---------------- scratch ----------------
__device__ float g_h[NN * H];
__device__ float g_h2[NN * H];
__device__ float g_tmp[NN * H];
__device__ float g_m[NE * H];
__device__ float g_mean[NN * H];
__device__ float g_std[NN * H];
__device__ float g_mn[NN * H];
__device__ float g_mx[NN * H];
__device__ int   g_cnt[NN];
__device__ int   g_start[NN + 1];
__device__ int   g_cursor[NN];
__device__ int   g_psrc[NE];
__device__ int   g_pdst[NE];
__device__ int   g_peid[NE];
__device__ float g_amp[NN];
__device__ float g_iamp[NN];
__device__ float g_Wcat[KCAT * H];
__device__ float g_T1[H * H];
__device__ float g_biasm[H];
__device__ float g_bn[2 * H];
__device__ float g_pool[NGR * H];
__device__ float g_z[NGR * 64];

// ---------------- tf32 mma helpers ----------------
// A tile: 128 rows x 16 k, stored swizzled: float4 slot s of row r lives at
// As4[r*4 + (s ^ ((r>>1)&3))]. Conflict-free for fill and fragment reads.
__device__ __forceinline__ unsigned ld_as(const float* As, int r, int slot, int c) {
    return __float_as_uint(As[r * 16 + ((slot ^ ((r >> 1) & 3)) << 2) + c]);
}

// Computes 16 k-steps of the 128x128 block product. acc[mt][nt][4].
__device__ __forceinline__ void mma_tile16(const float* As, const float* Ws,
                                           float (&acc)[4][4][4], int lane,
                                           int wm, int wn)
{
#pragma unroll
    for (int ks = 0; ks < 2; ks++) {
        unsigned b0[4], b1[4];
        int bk = ks * 8 + (lane & 3);
        int bn = wn * 32 + (lane >> 2);
#pragma unroll
        for (int nt = 0; nt < 4; nt++) {
            b0[nt] = __float_as_uint(Ws[bk * WS_STRIDE + bn + nt * 8]);
            b1[nt] = __float_as_uint(Ws[(bk + 4) * WS_STRIDE + bn + nt * 8]);
        }
#pragma unroll
        for (int mt = 0; mt < 4; mt++) {
            int r0 = wm * 64 + mt * 16 + (lane >> 2);
            int r1 = r0 + 8;
            int c = lane & 3;
            unsigned a0 = ld_as(As, r0, ks * 2,     c);
            unsigned a1 = ld_as(As, r1, ks * 2,     c);
            unsigned a2 = ld_as(As, r0, ks * 2 + 1, c);
            unsigned a3 = ld_as(As, r1, ks * 2 + 1, c);
#pragma unroll
            for (int nt = 0; nt < 4; nt++) {
                asm volatile(
                    "mma.sync.aligned.m16n8k8.row.col.f32.tf32.tf32.f32 "
                    "{%0,%1,%2,%3}, {%4,%5,%6,%7}, {%8,%9}, {%0,%1,%2,%3};"
                    : "+f"(acc[mt][nt][0]), "+f"(acc[mt][nt][1]),
                      "+f"(acc[mt][nt][2]), "+f"(acc[mt][nt][3])
                    : "r"(a0), "r"(a1), "r"(a2), "r"(a3),
                      "r"(b0[nt]), "r"(b1[nt]));
            }
        }
    }
}

// ---------------- fp32 tiled GEMM (small weight-prep only) ----------------
__global__ __launch_bounds__(256) void gemm128(
    const float* __restrict__ A, const float* __restrict__ W,
    const float* __restrict__ bias, float* __restrict__ C, int M, int K)
{
    __shared__ float As[16 * 132];
    __shared__ float Ws[16 * 128];
    int tid = threadIdx.x;
    int m0 = blockIdx.x * 128;
    int trow = tid >> 4, tcol = tid & 15;
    int r8 = trow * 8, c8 = tcol * 8;
    int arow = tid >> 2;
    int ac4 = (tid & 3) * 4;

    float acc[8][8];
#pragma unroll
    for (int i = 0; i < 8; i++)
#pragma unroll
        for (int j = 0; j < 8; j++) acc[i][j] = 0.f;

    for (int k0 = 0; k0 < K; k0 += 16) {
#pragma unroll
        for (int t = 0; t < 2; t++) {
            int r = arow + t * 64;
            int gr = m0 + r;
            float4 v = make_float4(0.f, 0.f, 0.f, 0.f);
            if (gr < M) v = *(const float4*)(A + (size_t)gr * K + k0 + ac4);
            As[(ac4 + 0) * 132 + r] = v.x;
            As[(ac4 + 1) * 132 + r] = v.y;
            As[(ac4 + 2) * 132 + r] = v.z;
            As[(ac4 + 3) * 132 + r] = v.w;
        }
#pragma unroll
        for (int t = 0; t < 2; t++) {
            int f4i = tid + t * 256;
            int wr = f4i >> 5, wc = (f4i & 31) * 4;
            *(float4*)&Ws[wr * 128 + wc] = *(const float4*)(W + (size_t)(k0 + wr) * 128 + wc);
        }
        __syncthreads();
#pragma unroll
        for (int kk = 0; kk < 16; kk++) {
            float4 a0 = *(const float4*)&As[kk * 132 + r8];
            float4 a1 = *(const float4*)&As[kk * 132 + r8 + 4];
            float4 w0 = *(const float4*)&Ws[kk * 128 + c8];
            float4 w1 = *(const float4*)&Ws[kk * 128 + c8 + 4];
            float a[8] = {a0.x, a0.y, a0.z, a0.w, a1.x, a1.y, a1.z, a1.w};
            float w[8] = {w0.x, w0.y, w0.z, w0.w, w1.x, w1.y, w1.z, w1.w};
#pragma unroll
            for (int i = 0; i < 8; i++)
#pragma unroll
                for (int j = 0; j < 8; j++) acc[i][j] += a[i] * w[j];
        }
        __syncthreads();
    }

    float b[8];
#pragma unroll
    for (int j = 0; j < 8; j++) b[j] = bias ? bias[c8 + j] : 0.f;
#pragma unroll
    for (int i = 0; i < 8; i++) {
        int gr = m0 + r8 + i;
        if (gr < M) {
            float4 o0, o1;
            o0.x = acc[i][0] + b[0]; o0.y = acc[i][1] + b[1];
            o0.z = acc[i][2] + b[2]; o0.w = acc[i][3] + b[3];
            o1.x = acc[i][4] + b[4]; o1.y = acc[i][5] + b[5];
            o1.z = acc[i][6] + b[6]; o1.w = acc[i][7] + b[7];
            *(float4*)(C + (size_t)gr * 128 + c8) = o0;
            *(float4*)(C + (size_t)gr * 128 + c8 + 4) = o1;
        }
    }
}

// ---------------- tensor-core generic GEMM: C[M,128] = A[M,K]@W[K,128] ----------------
__global__ __launch_bounds__(256) void gemm128t(
    const float* __restrict__ A, const float* __restrict__ W,
    const float* __restrict__ bias, float* __restrict__ C, int M, int K)
{
    __shared__ float As[128 * 16];
    __shared__ float Ws[16 * WS_STRIDE];
    int tid = threadIdx.x;
    int lane = tid & 31, warp = tid >> 5;
    int wm = warp >> 2, wn = warp & 3;
    int m0 = blockIdx.x * 128;
    int arow = tid >> 2;
    int slot = tid & 3;
    float4* As4 = (float4*)As;

    float acc[4][4][4];
#pragma unroll
    for (int a = 0; a < 4; a++)
#pragma unroll
        for (int b = 0; b < 4; b++)
#pragma unroll
            for (int c = 0; c < 4; c++) acc[a][b][c] = 0.f;

    for (int k0 = 0; k0 < K; k0 += 16) {
#pragma unroll
        for (int t = 0; t < 2; t++) {
            int r = arow + t * 64;
            int gr = m0 + r;
            float4 v = make_float4(0.f, 0.f, 0.f, 0.f);
            if (gr < M) v = *(const float4*)(A + (size_t)gr * K + k0 + slot * 4);
            As4[r * 4 + (slot ^ ((r >> 1) & 3))] = v;
        }
#pragma unroll
        for (int t = 0; t < 2; t++) {
            int f4i = tid + t * 256;
            int wr = f4i >> 5, wc = (f4i & 31) * 4;
            *(float4*)&Ws[wr * WS_STRIDE + wc] =
                *(const float4*)(W + (size_t)(k0 + wr) * 128 + wc);
        }
        __syncthreads();
        mma_tile16(As, Ws, acc, lane, wm, wn);
        __syncthreads();
    }

#pragma unroll
    for (int mt = 0; mt < 4; mt++) {
        int r0 = m0 + wm * 64 + mt * 16 + (lane >> 2);
#pragma unroll
        for (int nt = 0; nt < 4; nt++) {
            int col = wn * 32 + nt * 8 + 2 * (lane & 3);
            float b0 = bias ? bias[col] : 0.f;
            float b1 = bias ? bias[col + 1] : 0.f;
            if (r0 < M)
                *(float2*)(C + (size_t)r0 * 128 + col) =
                    make_float2(acc[mt][nt][0] + b0, acc[mt][nt][1] + b1);
            if (r0 + 8 < M)
                *(float2*)(C + (size_t)(r0 + 8) * 128 + col) =
                    make_float2(acc[mt][nt][2] + b0, acc[mt][nt][3] + b1);
        }
    }
}

// ---------------- tensor-core edge message GEMM (gathered A, sorted edges) ----------------
__global__ __launch_bounds__(256) void edge_msgt(const float* __restrict__ edge_attr)
{
    __shared__ float As[128 * 16];
    __shared__ float Ws[16 * WS_STRIDE];
    __shared__ int sdst[128], ssrc[128], seid[128];
    int tid = threadIdx.x;
    int lane = tid & 31, warp = tid >> 5;
    int wm = warp >> 2, wn = warp & 3;
    int e0 = blockIdx.x * 128;
    int arow = tid >> 2;
    int slot = tid & 3;
    float4* As4 = (float4*)As;

    if (tid < 128) {
        int p = e0 + tid;
        sdst[tid] = g_pdst[p];
        ssrc[tid] = g_psrc[p];
        seid[tid] = g_peid[p];
    }
    __syncthreads();

    float acc[4][4][4];
#pragma unroll
    for (int a = 0; a < 4; a++)
#pragma unroll
        for (int b = 0; b < 4; b++)
#pragma unroll
            for (int c = 0; c < 4; c++) acc[a][b][c] = 0.f;

    for (int kt = 0; kt < 17; kt++) {
#pragma unroll
        for (int t = 0; t < 2; t++) {
            int r = arow + t * 64;
            float4 v;
            if (kt < 8)
                v = *(const float4*)(g_h + (size_t)sdst[r] * H + kt * 16 + slot * 4);
            else if (kt < 16)
                v = *(const float4*)(g_h + (size_t)ssrc[r] * H + (kt - 8) * 16 + slot * 4);
            else
                v = *(const float4*)(edge_attr + (size_t)seid[r] * 16 + slot * 4);
            As4[r * 4 + (slot ^ ((r >> 1) & 3))] = v;
        }
#pragma unroll
        for (int t = 0; t < 2; t++) {
            int f4i = tid + t * 256;
            int wr = f4i >> 5, wc = (f4i & 31) * 4;
            *(float4*)&Ws[wr * WS_STRIDE + wc] =
                *(const float4*)(g_Wcat + (size_t)(kt * 16 + wr) * 128 + wc);
        }
        __syncthreads();
        mma_tile16(As, Ws, acc, lane, wm, wn);
        __syncthreads();
    }

#pragma unroll
    for (int mt = 0; mt < 4; mt++) {
        int r0 = e0 + wm * 64 + mt * 16 + (lane >> 2);
#pragma unroll
        for (int nt = 0; nt < 4; nt++) {
            int col = wn * 32 + nt * 8 + 2 * (lane & 3);
            float b0 = g_biasm[col], b1 = g_biasm[col + 1];
            *(float2*)(g_m + (size_t)r0 * 128 + col) =
                make_float2(acc[mt][nt][0] + b0, acc[mt][nt][1] + b1);
            *(float2*)(g_m + (size_t)(r0 + 8) * 128 + col) =
                make_float2(acc[mt][nt][2] + b0, acc[mt][nt][3] + b1);
        }
    }
}

// ---------------- tensor-core post-NN gather-GEMM (virtual [N,13H] A) ----------------
__global__ __launch_bounds__(256) void post_gemmt(const float* __restrict__ W,
                                                  const float* __restrict__ bias)
{
    __shared__ float As[128 * 16];
    __shared__ float Ws[16 * WS_STRIDE];
    __shared__ float samp[128], siamp[128];
    int tid = threadIdx.x;
    int lane = tid & 31, warp = tid >> 5;
    int wm = warp >> 2, wn = warp & 3;
    int n0 = blockIdx.x * 128;
    int arow = tid >> 2;
    int slot = tid & 3;
    float4* As4 = (float4*)As;

    if (tid < 128)      { int n = n0 + tid;       samp[tid] = (n < NN) ? g_amp[n] : 1.f; }
    else                { int n = n0 + tid - 128; siamp[tid - 128] = (n < NN) ? g_iamp[n] : 1.f; }
    __syncthreads();

    float acc[4][4][4];
#pragma unroll
    for (int a = 0; a < 4; a++)
#pragma unroll
        for (int b = 0; b < 4; b++)
#pragma unroll
            for (int c = 0; c < 4; c++) acc[a][b][c] = 0.f;

    for (int kt = 0; kt < 104; kt++) {
        int b = kt >> 3;
        int kk0 = (kt & 7) * 16;
        const float* src;
        if (b == 0) src = g_h;
        else {
            int a = (b - 1) & 3;
            src = (a == 0) ? g_mean : (a == 1) ? g_mn : (a == 2) ? g_mx : g_std;
        }
#pragma unroll
        for (int t = 0; t < 2; t++) {
            int r = arow + t * 64;
            int n = n0 + r;
            float4 v = make_float4(0.f, 0.f, 0.f, 0.f);
            if (n < NN) {
                v = *(const float4*)(src + (size_t)n * H + kk0 + slot * 4);
                float s = (b <= 4) ? 1.f : (b <= 8) ? samp[r] : siamp[r];
                v.x *= s; v.y *= s; v.z *= s; v.w *= s;
            }
            As4[r * 4 + (slot ^ ((r >> 1) & 3))] = v;
        }
#pragma unroll
        for (int t = 0; t < 2; t++) {
            int f4i = tid + t * 256;
            int wr = f4i >> 5, wc = (f4i & 31) * 4;
            *(float4*)&Ws[wr * WS_STRIDE + wc] =
                *(const float4*)(W + (size_t)(kt * 16 + wr) * 128 + wc);
        }
        __syncthreads();
        mma_tile16(As, Ws, acc, lane, wm, wn);
        __syncthreads();
    }

#pragma unroll
    for (int mt = 0; mt < 4; mt++) {
        int r0 = n0 + wm * 64 + mt * 16 + (lane >> 2);
#pragma unroll
        for (int nt = 0; nt < 4; nt++) {
            int col = wn * 32 + nt * 8 + 2 * (lane & 3);
            float b0 = bias[col], b1 = bias[col + 1];
            if (r0 < NN)
                *(float2*)(g_tmp + (size_t)r0 * 128 + col) =
                    make_float2(acc[mt][nt][0] + b0, acc[mt][nt][1] + b1);
            if (r0 + 8 < NN)
                *(float2*)(g_tmp + (size_t)(r0 + 8) * 128 + col) =
                    make_float2(acc[mt][nt][2] + b0, acc[mt][nt][3] + b1);
        }
    }
}

// ---------------- node-centric segmented aggregation ----------------
__global__ __launch_bounds__(128) void agg_k()
{
    int n = blockIdx.x;
    int c = threadIdx.x;
    int start = g_start[n];
    int cnt = g_start[n + 1] - start;
    float s = 0.f, q = 0.f, mn = INFINITY, mx = -INFINITY;
    for (int i = 0; i < cnt; i++) {
        float v = g_m[(size_t)(start + i) * 128 + c];
        s += v; q += v * v;
        mn = fminf(mn, v); mx = fmaxf(mx, v);
    }
    float degc = fmaxf((float)cnt, 1.f);
    float inv = 1.f / degc;
    float mean = s * inv;
    float var = fmaxf(q * inv - mean * mean, 0.f);
    size_t idx = (size_t)n * 128 + c;
    g_mean[idx] = mean;
    g_std[idx] = sqrtf(var + EPS_STD);
    g_mn[idx] = (cnt > 0) ? mn : 0.f;
    g_mx[idx] = (cnt > 0) ? mx : 0.f;
}

// ---------------- sorting + small kernels ----------------
__global__ void init_cnt() {
    int idx = blockIdx.x * blockDim.x + threadIdx.x;
    if (idx < NN) g_cnt[idx] = 0;
}
__global__ void deg_count(const int* __restrict__ dstI) {
    int e = blockIdx.x * blockDim.x + threadIdx.x;
    if (e < NE) atomicAdd(&g_cnt[dstI[e]], 1);
}
__global__ __launch_bounds__(1024) void scan_k() {
    __shared__ int warp_sums[32];
    int t = threadIdx.x;
    int lane = t & 31, wid = t >> 5;
    int base = t * 30;
    int s = 0;
#pragma unroll
    for (int i = 0; i < 30; i++) {
        int n = base + i;
        if (n < NN) s += g_cnt[n];
    }
    int v = s;
#pragma unroll
    for (int off = 1; off < 32; off <<= 1) {
        int u = __shfl_up_sync(0xffffffffu, v, off);
        if (lane >= off) v += u;
    }
    if (lane == 31) warp_sums[wid] = v;
    __syncthreads();
    if (wid == 0) {
        int w = warp_sums[lane];
#pragma unroll
        for (int off = 1; off < 32; off <<= 1) {
            int u = __shfl_up_sync(0xffffffffu, w, off);
            if (lane >= off) w += u;
        }
        warp_sums[lane] = w;
    }
    __syncthreads();
    int run = v - s + (wid > 0 ? warp_sums[wid - 1] : 0);
#pragma unroll
    for (int i = 0; i < 30; i++) {
        int n = base + i;
        if (n < NN) { g_start[n] = run; g_cursor[n] = run; run += g_cnt[n]; }
    }
    if (t == 1023) g_start[NN] = run;
}
__global__ void scatter_k(const int* __restrict__ srcI, const int* __restrict__ dstI) {
    int e = blockIdx.x * blockDim.x + threadIdx.x;
    if (e >= NE) return;
    int d = dstI[e];
    int p = atomicAdd(&g_cursor[d], 1);
    g_psrc[p] = srcI[e];
    g_pdst[p] = d;
    g_peid[p] = e;
}
__global__ void copy_wcat(const float* __restrict__ preW) {
    int idx = blockIdx.x * blockDim.x + threadIdx.x;
    if (idx < 256 * H) g_Wcat[idx] = preW[idx];
}
__global__ void biasm_k(const float* __restrict__ be, const float* __restrict__ eb,
                        const float* __restrict__ P2, const float* __restrict__ pb) {
    int j = threadIdx.x;
    float s = pb[j];
    for (int k = 0; k < 16; k++)  s += be[k] * g_T1[k * H + j];
    for (int k = 0; k < H; k++)   s += eb[k] * P2[k * H + j];
    g_biasm[j] = s;
}
__global__ void amp_k() {
    int n = blockIdx.x * blockDim.x + threadIdx.x;
    if (n >= NN) return;
    float degc = fmaxf((float)g_cnt[n], 1.f);
    float a = logf(degc + 1.f) / AVG_LOG;
    g_amp[n] = a;
    g_iamp[n] = 1.f / a;
}
__global__ void bn_zero() { g_bn[threadIdx.x] = 0.f; }
__global__ void bn_stats() {
    int tid = threadIdx.x;
    int half = tid >> 7;
    float s = 0.f, q = 0.f;
    for (int row = blockIdx.x * 2 + half; row < NN; row += gridDim.x * 2) {
        float v = g_h2[(size_t)row * H + (tid & 127)];
        s += v; q += v * v;
    }
    __shared__ float sh[256];
    sh[tid] = s; __syncthreads();
    if (tid < 128) atomicAdd(&g_bn[tid], sh[tid] + sh[tid + 128]);
    __syncthreads();
    sh[tid] = q; __syncthreads();
    if (tid < 128) atomicAdd(&g_bn[128 + tid], sh[tid] + sh[tid + 128]);
}
__global__ void bn_norm(const float* __restrict__ gamma, const float* __restrict__ beta) {
    int idx = blockIdx.x * blockDim.x + threadIdx.x;
    if (idx >= NN * H) return;
    int c = idx & 127;
    const float invN = 1.f / (float)NN;
    float mu = g_bn[c] * invN;
    float var = g_bn[128 + c] * invN - mu * mu;
    float y = (g_h2[idx] - mu) * rsqrtf(var + EPS_BN) * gamma[c] + beta[c];
    g_h[idx] = fmaxf(y, 0.f);
}
__global__ void init_pool() {
    int idx = blockIdx.x * blockDim.x + threadIdx.x;
    if (idx < NGR * H) g_pool[idx] = 0.f;
}
__global__ void pool_k(const int* __restrict__ batch) {
    int c = threadIdx.x;
    int start = blockIdx.x * 256;
    int end = min(start + 256, NN);
    if (start >= NN) return;
    float acc = 0.f;
    int cur = batch[start];
    for (int n = start; n < end; n++) {
        int g = batch[n];
        if (g != cur) { atomicAdd(&g_pool[cur * H + c], acc); acc = 0.f; cur = g; }
        acc += g_h[(size_t)n * H + c];
    }
    atomicAdd(&g_pool[cur * H + c], acc);
}
__global__ void head1_k(const float* __restrict__ W1, const float* __restrict__ b1) {
    int idx = blockIdx.x * blockDim.x + threadIdx.x;
    if (idx >= NGR * 64) return;
    int g = idx >> 6, j = idx & 63;
    float s = b1[j];
    for (int k = 0; k < H; k++) s += g_pool[g * H + k] * W1[k * 64 + j];
    g_z[idx] = fmaxf(s, 0.f);
}
__global__ void head2_k(const float* __restrict__ W2, const float* __restrict__ b2,
                        float* __restrict__ out) {
    int idx = blockIdx.x * blockDim.x + threadIdx.x;
    if (idx >= NGR * NOUT) return;
    int g = idx / NOUT, j = idx % NOUT;
    float s = b2[j];
    for (int k = 0; k < 64; k++) s += g_z[g * 64 + k] * W2[k * NOUT + j];
    out[idx] = s;
}

// ---------------- launch ----------------
extern "C" void kernel_launch(void* const* d_in, const int* in_sizes, int n_in,
                              void* d_out, int out_size)
{
    int iEI = 1, iBatch = 2, iEA = 3;
    if (in_sizes[1] == NE * 16) { iEA = 1; iEI = 2; iBatch = 3; }

    const float* x         = (const float*)d_in[0];
    const int*   edge_index= (const int*)  d_in[iEI];
    const int*   batch     = (const int*)  d_in[iBatch];
    const float* edge_attr = (const float*)d_in[iEA];
    const float* node_emb_W= (const float*)d_in[4];
    const float* node_emb_b= (const float*)d_in[5];
    const float* edge_emb_W= (const float*)d_in[6];
    const float* edge_emb_b= (const float*)d_in[7];
    const float* edge_enc_W= (const float*)d_in[8];
    const float* edge_enc_b= (const float*)d_in[9];
    const float* pre_W     = (const float*)d_in[10];
    const float* pre_b     = (const float*)d_in[11];
    const float* post_W    = (const float*)d_in[12];
    const float* post_b    = (const float*)d_in[13];
    const float* lin_W     = (const float*)d_in[14];
    const float* lin_b     = (const float*)d_in[15];
    const float* bn_gamma  = (const float*)d_in[16];
    const float* bn_beta   = (const float*)d_in[17];
    const float* head1_W   = (const float*)d_in[18];
    const float* head1_b   = (const float*)d_in[19];
    const float* head2_W   = (const float*)d_in[20];
    const float* head2_b   = (const float*)d_in[21];

    const int* srcI = edge_index;
    const int* dstI = edge_index + NE;

    float *p_h, *p_h2, *p_tmp, *p_wcat, *p_T1;
    cudaGetSymbolAddress((void**)&p_h,    g_h);
    cudaGetSymbolAddress((void**)&p_h2,   g_h2);
    cudaGetSymbolAddress((void**)&p_tmp,  g_tmp);
    cudaGetSymbolAddress((void**)&p_wcat, g_Wcat);
    cudaGetSymbolAddress((void**)&p_T1,   g_T1);

    // Node embedding (tensor core)
    gemm128t<<<(NN + 127) / 128, 256>>>(x, node_emb_W, node_emb_b, p_h, NN, 64);

    // Sort edges by dst (layer-invariant)
    init_cnt<<<(NN + 255) / 256, 256>>>();
    deg_count<<<(NE + 255) / 256, 256>>>(dstI);
    scan_k<<<1, 1024>>>();
    scatter_k<<<(NE + 255) / 256, 256>>>(srcI, dstI);
    amp_k<<<(NN + 255) / 256, 256>>>();

    for (int l = 0; l < NL; l++) {
        const float* preWl = pre_W + (size_t)l * 384 * H;
        const float* P2 = preWl + 256 * H;
        copy_wcat<<<128, 256>>>(preWl);
        gemm128<<<1, 256>>>(edge_enc_W + (size_t)l * H * H, P2,
                            (const float*)nullptr, p_T1, 128, 128);
        gemm128<<<1, 256>>>(edge_emb_W, p_T1,
                            (const float*)nullptr, p_wcat + 256 * H, 16, 128);
        biasm_k<<<1, 128>>>(edge_emb_b, edge_enc_b + l * H, P2, pre_b + l * H);

        edge_msgt<<<NE / 128, 256>>>(edge_attr);
        agg_k<<<NN, 128>>>();

        post_gemmt<<<(NN + 127) / 128, 256>>>(post_W + (size_t)l * 13 * H * H, post_b + l * H);
        gemm128t<<<(NN + 127) / 128, 256>>>(p_tmp, lin_W + (size_t)l * H * H,
                                            lin_b + l * H, p_h2, NN, H);

        bn_zero<<<1, 256>>>();
        bn_stats<<<128, 256>>>();
        bn_norm<<<(NN * H + 255) / 256, 256>>>(bn_gamma + l * H, bn_beta + l * H);
    }

    init_pool<<<16, 256>>>();
    pool_k<<<(NN + 255) / 256, 128>>>(batch);
    head1_k<<<8, 256>>>(head1_W, head1_b);
    head2_k<<<2, 256>>>(head2_W, head2_b, (float*)d_out);
}

// round 5
// speedup vs baseline: 4.4884x; 1.2659x over previous
#include <cuda_runtime.h>
#include <math.h>

#define NN 30000
#define NE 480000
#define H 128
#define NL 4
#define NGR 32
#define NOUT 12
#define AVG_LOG 1.38214548f
#define EPS_BN 1e-5f
#define EPS_STD 1e-5f
#define KCAT 272
#define WS_STRIDE 136
#define SCAN_B 128
#define CHUNK 235           // ceil(NN/SCAN_B)
#define EDGE_SMEM (128 * 132 * 4)   // 67584 bytes

// ---------------- scratch ----------------
__device__ float g_h[NN * H];
__device__ float g_h2[NN * H];
__device__ float g_tmp[NN * H];
__device__ float g_mean[NN * H];
__device__ float g_std[NN * H];
__device__ float g_mn[NN * H];
__device__ float g_mx[NN * H];
__device__ float g_bsum[NN * H];
__device__ float g_bsq[NN * H];
__device__ float g_bmn[NN * H];
__device__ float g_bmx[NN * H];
__device__ int   g_cnt[NN];
__device__ int   g_start[NN + 1];
__device__ int   g_cursor[NN];
__device__ int   g_part[SCAN_B];
__device__ int   g_psrc[NE];
__device__ int   g_pdst[NE];
__device__ int   g_peid[NE];
__device__ int   g_blist[NN];
__device__ int   g_bcnt;
__device__ float g_amp[NN];
__device__ float g_iamp[NN];
__device__ float g_WcatL[NL * KCAT * H];
__device__ float g_T1[H * H];
__device__ float g_biasmL[NL * H];
__device__ float g_bn[2 * H];
__device__ float g_pool[NGR * H];
__device__ float g_z[NGR * 64];

// ---------------- helpers ----------------
__device__ __forceinline__ void atomicMaxF(float* a, float v) {
    if (v >= 0.f) atomicMax((int*)a, __float_as_int(v));
    else          atomicMin((unsigned int*)a, __float_as_uint(v));
}
__device__ __forceinline__ void atomicMinF(float* a, float v) {
    if (v >= 0.f) atomicMin((int*)a, __float_as_int(v));
    else          atomicMax((unsigned int*)a, __float_as_uint(v));
}
__device__ __forceinline__ void cp16(float* smem, const float* g) {
    unsigned sa = (unsigned)__cvta_generic_to_shared(smem);
    asm volatile("cp.async.cg.shared.global [%0], [%1], 16;\n" :: "r"(sa), "l"(g));
}
__device__ __forceinline__ void cp16p(float* smem, const float* g, bool pred) {
    unsigned sa = (unsigned)__cvta_generic_to_shared(smem);
    int sz = pred ? 16 : 0;
    asm volatile("cp.async.cg.shared.global [%0], [%1], 16, %2;\n" :: "r"(sa), "l"(g), "r"(sz));
}
#define CP_COMMIT() asm volatile("cp.async.commit_group;\n" ::: "memory")
#define CP_WAIT1()  asm volatile("cp.async.wait_group 1;\n" ::: "memory")
#define CP_WAIT0()  asm volatile("cp.async.wait_group 0;\n" ::: "memory")

// post-GEMM tile order: group3 (kt 72..103), group2 (kt 40..71), group01 (kt 0..39)
__device__ __forceinline__ int map_kt(int t) {
    return (t < 32) ? 72 + t : (t < 64) ? 40 + (t - 32) : (t - 64);
}

// A tile swizzle: float4 slot s of row r -> As4[r*4 + (s ^ ((r>>1)&3))]
__device__ __forceinline__ unsigned ld_as(const float* As, int r, int slot, int c) {
    return __float_as_uint(As[r * 16 + ((slot ^ ((r >> 1) & 3)) << 2) + c]);
}

__device__ __forceinline__ void mma_tile16(const float* As, const float* Ws,
                                           float (&acc)[4][4][4], int lane,
                                           int wm, int wn)
{
#pragma unroll
    for (int ks = 0; ks < 2; ks++) {
        unsigned b0[4], b1[4];
        int bk = ks * 8 + (lane & 3);
        int bn = wn * 32 + (lane >> 2);
#pragma unroll
        for (int nt = 0; nt < 4; nt++) {
            b0[nt] = __float_as_uint(Ws[bk * WS_STRIDE + bn + nt * 8]);
            b1[nt] = __float_as_uint(Ws[(bk + 4) * WS_STRIDE + bn + nt * 8]);
        }
#pragma unroll
        for (int mt = 0; mt < 4; mt++) {
            int r0 = wm * 64 + mt * 16 + (lane >> 2);
            int r1 = r0 + 8;
            int c = lane & 3;
            unsigned a0 = ld_as(As, r0, ks * 2,     c);
            unsigned a1 = ld_as(As, r1, ks * 2,     c);
            unsigned a2 = ld_as(As, r0, ks * 2 + 1, c);
            unsigned a3 = ld_as(As, r1, ks * 2 + 1, c);
#pragma unroll
            for (int nt = 0; nt < 4; nt++) {
                asm volatile(
                    "mma.sync.aligned.m16n8k8.row.col.f32.tf32.tf32.f32 "
                    "{%0,%1,%2,%3}, {%4,%5,%6,%7}, {%8,%9}, {%0,%1,%2,%3};"
                    : "+f"(acc[mt][nt][0]), "+f"(acc[mt][nt][1]),
                      "+f"(acc[mt][nt][2]), "+f"(acc[mt][nt][3])
                    : "r"(a0), "r"(a1), "r"(a2), "r"(a3),
                      "r"(b0[nt]), "r"(b1[nt]));
            }
        }
    }
}

// ---------------- fp32 tiled GEMM (weight-prep only) ----------------
__global__ __launch_bounds__(256) void gemm128(
    const float* __restrict__ A, const float* __restrict__ W,
    const float* __restrict__ bias, float* __restrict__ C, int M, int K)
{
    __shared__ float As[16 * 132];
    __shared__ float Ws[16 * 128];
    int tid = threadIdx.x;
    int m0 = blockIdx.x * 128;
    int trow = tid >> 4, tcol = tid & 15;
    int r8 = trow * 8, c8 = tcol * 8;
    int arow = tid >> 2;
    int ac4 = (tid & 3) * 4;

    float acc[8][8];
#pragma unroll
    for (int i = 0; i < 8; i++)
#pragma unroll
        for (int j = 0; j < 8; j++) acc[i][j] = 0.f;

    for (int k0 = 0; k0 < K; k0 += 16) {
#pragma unroll
        for (int t = 0; t < 2; t++) {
            int r = arow + t * 64;
            int gr = m0 + r;
            float4 v = make_float4(0.f, 0.f, 0.f, 0.f);
            if (gr < M) v = *(const float4*)(A + (size_t)gr * K + k0 + ac4);
            As[(ac4 + 0) * 132 + r] = v.x;
            As[(ac4 + 1) * 132 + r] = v.y;
            As[(ac4 + 2) * 132 + r] = v.z;
            As[(ac4 + 3) * 132 + r] = v.w;
        }
#pragma unroll
        for (int t = 0; t < 2; t++) {
            int f4i = tid + t * 256;
            int wr = f4i >> 5, wc = (f4i & 31) * 4;
            *(float4*)&Ws[wr * 128 + wc] = *(const float4*)(W + (size_t)(k0 + wr) * 128 + wc);
        }
        __syncthreads();
#pragma unroll
        for (int kk = 0; kk < 16; kk++) {
            float4 a0 = *(const float4*)&As[kk * 132 + r8];
            float4 a1 = *(const float4*)&As[kk * 132 + r8 + 4];
            float4 w0 = *(const float4*)&Ws[kk * 128 + c8];
            float4 w1 = *(const float4*)&Ws[kk * 128 + c8 + 4];
            float a[8] = {a0.x, a0.y, a0.z, a0.w, a1.x, a1.y, a1.z, a1.w};
            float w[8] = {w0.x, w0.y, w0.z, w0.w, w1.x, w1.y, w1.z, w1.w};
#pragma unroll
            for (int i = 0; i < 8; i++)
#pragma unroll
                for (int j = 0; j < 8; j++) acc[i][j] += a[i] * w[j];
        }
        __syncthreads();
    }

    float b[8];
#pragma unroll
    for (int j = 0; j < 8; j++) b[j] = bias ? bias[c8 + j] : 0.f;
#pragma unroll
    for (int i = 0; i < 8; i++) {
        int gr = m0 + r8 + i;
        if (gr < M) {
            float4 o0, o1;
            o0.x = acc[i][0] + b[0]; o0.y = acc[i][1] + b[1];
            o0.z = acc[i][2] + b[2]; o0.w = acc[i][3] + b[3];
            o1.x = acc[i][4] + b[4]; o1.y = acc[i][5] + b[5];
            o1.z = acc[i][6] + b[6]; o1.w = acc[i][7] + b[7];
            *(float4*)(C + (size_t)gr * 128 + c8) = o0;
            *(float4*)(C + (size_t)gr * 128 + c8 + 4) = o1;
        }
    }
}

// ---------------- tensor-core generic GEMM (emb / lin) ----------------
__global__ __launch_bounds__(256) void gemm128t(
    const float* __restrict__ A, const float* __restrict__ W,
    const float* __restrict__ bias, float* __restrict__ C, int M, int K)
{
    __shared__ float As[128 * 16];
    __shared__ float Ws[16 * WS_STRIDE];
    int tid = threadIdx.x;
    int lane = tid & 31, warp = tid >> 5;
    int wm = warp >> 2, wn = warp & 3;
    int m0 = blockIdx.x * 128;
    int arow = tid >> 2;
    int slot = tid & 3;
    float4* As4 = (float4*)As;

    float acc[4][4][4];
#pragma unroll
    for (int a = 0; a < 4; a++)
#pragma unroll
        for (int b = 0; b < 4; b++)
#pragma unroll
            for (int c = 0; c < 4; c++) acc[a][b][c] = 0.f;

    for (int k0 = 0; k0 < K; k0 += 16) {
#pragma unroll
        for (int t = 0; t < 2; t++) {
            int r = arow + t * 64;
            int gr = m0 + r;
            float4 v = make_float4(0.f, 0.f, 0.f, 0.f);
            if (gr < M) v = *(const float4*)(A + (size_t)gr * K + k0 + slot * 4);
            As4[r * 4 + (slot ^ ((r >> 1) & 3))] = v;
        }
#pragma unroll
        for (int t = 0; t < 2; t++) {
            int f4i = tid + t * 256;
            int wr = f4i >> 5, wc = (f4i & 31) * 4;
            *(float4*)&Ws[wr * WS_STRIDE + wc] =
                *(const float4*)(W + (size_t)(k0 + wr) * 128 + wc);
        }
        __syncthreads();
        mma_tile16(As, Ws, acc, lane, wm, wn);
        __syncthreads();
    }

#pragma unroll
    for (int mt = 0; mt < 4; mt++) {
        int r0 = m0 + wm * 64 + mt * 16 + (lane >> 2);
#pragma unroll
        for (int nt = 0; nt < 4; nt++) {
            int col = wn * 32 + nt * 8 + 2 * (lane & 3);
            float b0 = bias ? bias[col] : 0.f;
            float b1 = bias ? bias[col + 1] : 0.f;
            if (r0 < M)
                *(float2*)(C + (size_t)r0 * 128 + col) =
                    make_float2(acc[mt][nt][0] + b0, acc[mt][nt][1] + b1);
            if (r0 + 8 < M)
                *(float2*)(C + (size_t)(r0 + 8) * 128 + col) =
                    make_float2(acc[mt][nt][2] + b0, acc[mt][nt][3] + b1);
        }
    }
}

// ---------------- fused edge message GEMM + segmented aggregation ----------------
__global__ __launch_bounds__(256) void edge_agg(const float* __restrict__ edge_attr,
                                                const float* __restrict__ Wcat,
                                                const float* __restrict__ biasm)
{
    extern __shared__ float s_dyn[];
    float* As = s_dyn;            // 2 stages x 2048 floats
    float* Ws = s_dyn + 4096;     // 2 stages x 2176 floats
    float* mt_ = s_dyn;           // m tile [128 x 132], reused after compute
    __shared__ int sdst[128], ssrc[128], seid[128];

    int tid = threadIdx.x;
    int lane = tid & 31, warp = tid >> 5;
    int wm = warp >> 2, wn = warp & 3;
    int e0 = blockIdx.x * 128;
    int arow = tid >> 2;
    int slot = tid & 3;

    if (tid < 128) {
        int p = e0 + tid;
        sdst[tid] = g_pdst[p];
        ssrc[tid] = g_psrc[p];
        seid[tid] = g_peid[p];
    }
    __syncthreads();

    float acc[4][4][4];
#pragma unroll
    for (int a = 0; a < 4; a++)
#pragma unroll
        for (int b = 0; b < 4; b++)
#pragma unroll
            for (int c = 0; c < 4; c++) acc[a][b][c] = 0.f;

    auto load_tile = [&](int kt, int st) {
#pragma unroll
        for (int t = 0; t < 2; t++) {
            int r = arow + t * 64;
            const float* src;
            if (kt < 8)       src = g_h + (size_t)sdst[r] * H + kt * 16 + slot * 4;
            else if (kt < 16) src = g_h + (size_t)ssrc[r] * H + (kt - 8) * 16 + slot * 4;
            else              src = edge_attr + (size_t)seid[r] * 16 + slot * 4;
            cp16(&As[st * 2048 + r * 16 + ((slot ^ ((r >> 1) & 3)) << 2)], src);
        }
#pragma unroll
        for (int t = 0; t < 2; t++) {
            int f4i = tid + t * 256;
            int wr = f4i >> 5, wc = (f4i & 31) * 4;
            cp16(&Ws[st * 2176 + wr * WS_STRIDE + wc],
                 Wcat + (size_t)(kt * 16 + wr) * 128 + wc);
        }
    };

    load_tile(0, 0);
    CP_COMMIT();
    for (int kt = 0; kt < 17; kt++) {
        if (kt < 16) { load_tile(kt + 1, (kt + 1) & 1); CP_COMMIT(); CP_WAIT1(); }
        else CP_WAIT0();
        __syncthreads();
        mma_tile16(&As[(kt & 1) * 2048], &Ws[(kt & 1) * 2176], acc, lane, wm, wn);
        __syncthreads();
    }

    // write message tile (+bias) to SMEM
#pragma unroll
    for (int mt2 = 0; mt2 < 4; mt2++) {
        int r0 = wm * 64 + mt2 * 16 + (lane >> 2);
#pragma unroll
        for (int nt = 0; nt < 4; nt++) {
            int col = wn * 32 + nt * 8 + 2 * (lane & 3);
            float b0 = biasm[col], b1 = biasm[col + 1];
            *(float2*)&mt_[r0 * 132 + col] =
                make_float2(acc[mt2][nt][0] + b0, acc[mt2][nt][1] + b1);
            *(float2*)&mt_[(r0 + 8) * 132 + col] =
                make_float2(acc[mt2][nt][2] + b0, acc[mt2][nt][3] + b1);
        }
    }
    __syncthreads();

    // segmented reduce: interior nodes final, boundary nodes via atomics
    int c = tid & 127, g2 = tid >> 7;
    int nfirst = sdst[0], nlast = sdst[127];
    for (int n = nfirst + g2; n <= nlast; n += 2) {
        int s = g_start[n], e = g_start[n + 1];
        if (s == e) continue;
        int lo = max(s, e0), hi = min(e, e0 + 128);
        if (lo >= hi) continue;
        float sumv = 0.f, sq = 0.f, mn = INFINITY, mx = -INFINITY;
        for (int r = lo - e0; r < hi - e0; r++) {
            float v = mt_[r * 132 + c];
            sumv += v; sq += v * v;
            mn = fminf(mn, v); mx = fmaxf(mx, v);
        }
        size_t idx = (size_t)n * H + c;
        if (s >= e0 && e <= e0 + 128) {
            float degc = (float)(e - s);
            float inv = 1.f / degc;
            float mean = sumv * inv;
            float var = fmaxf(sq * inv - mean * mean, 0.f);
            g_mean[idx] = mean;
            g_std[idx] = sqrtf(var + EPS_STD);
            g_mn[idx] = mn;
            g_mx[idx] = mx;
        } else {
            atomicAdd(&g_bsum[idx], sumv);
            atomicAdd(&g_bsq[idx], sq);
            atomicMinF(&g_bmn[idx], mn);
            atomicMaxF(&g_bmx[idx], mx);
        }
    }
}

// ---------------- boundary helpers ----------------
__global__ void bnd_build() {
    int n = blockIdx.x * blockDim.x + threadIdx.x;
    if (n >= NN) return;
    int s = g_start[n], e = g_start[n + 1];
    bool bnd = (s == e) || ((s >> 7) != ((e - 1) >> 7));
    if (bnd) {
        int p = atomicAdd(&g_bcnt, 1);
        g_blist[p] = n;
    }
}
__global__ void init_bnd() {
    int B = g_bcnt;
    int total = B * 128;
    for (int i = blockIdx.x * blockDim.x + threadIdx.x; i < total;
         i += gridDim.x * blockDim.x) {
        int n = g_blist[i >> 7];
        int c = i & 127;
        size_t idx = (size_t)n * H + c;
        g_bsum[idx] = 0.f; g_bsq[idx] = 0.f;
        g_bmn[idx] = INFINITY; g_bmx[idx] = -INFINITY;
    }
}
__global__ void fin_bnd() {
    int B = g_bcnt;
    int total = B * 128;
    for (int i = blockIdx.x * blockDim.x + threadIdx.x; i < total;
         i += gridDim.x * blockDim.x) {
        int n = g_blist[i >> 7];
        int c = i & 127;
        size_t idx = (size_t)n * H + c;
        int cnt = g_start[n + 1] - g_start[n];
        if (cnt == 0) {
            g_mean[idx] = 0.f; g_std[idx] = sqrtf(EPS_STD);
            g_mn[idx] = 0.f; g_mx[idx] = 0.f;
        } else {
            float inv = 1.f / (float)cnt;
            float mean = g_bsum[idx] * inv;
            float var = fmaxf(g_bsq[idx] * inv - mean * mean, 0.f);
            g_mean[idx] = mean;
            g_std[idx] = sqrtf(var + EPS_STD);
            g_mn[idx] = g_bmn[idx];
            g_mx[idx] = g_bmx[idx];
        }
    }
}

// ---------------- post-NN gather-GEMM, pipelined, group-reordered scaling ----------------
__global__ __launch_bounds__(256) void post_gemmt(const float* __restrict__ W,
                                                  const float* __restrict__ bias)
{
    __shared__ float As[2][128 * 16];
    __shared__ float Ws[2][16 * WS_STRIDE];
    int tid = threadIdx.x;
    int lane = tid & 31, warp = tid >> 5;
    int wm = warp >> 2, wn = warp & 3;
    int n0 = blockIdx.x * 128;
    int arow = tid >> 2;
    int slot = tid & 3;

    // per-thread row amp factors
    float sa[8], si2[8];
#pragma unroll
    for (int mt = 0; mt < 4; mt++)
#pragma unroll
        for (int hh = 0; hh < 2; hh++) {
            int n = n0 + wm * 64 + mt * 16 + (lane >> 2) + hh * 8;
            if (n >= NN) n = NN - 1;
            float a = g_amp[n], ia = g_iamp[n];
            sa[mt * 2 + hh] = a;
            si2[mt * 2 + hh] = ia * ia;
        }

    float acc[4][4][4];
#pragma unroll
    for (int a = 0; a < 4; a++)
#pragma unroll
        for (int b = 0; b < 4; b++)
#pragma unroll
            for (int c = 0; c < 4; c++) acc[a][b][c] = 0.f;

    auto load_tile = [&](int t, int st) {
        int kt = map_kt(t);
        int b = kt >> 3;
        const float* srcb;
        if (b == 0) srcb = g_h;
        else {
            int a = (b - 1) & 3;
            srcb = (a == 0) ? g_mean : (a == 1) ? g_mn : (a == 2) ? g_mx : g_std;
        }
        int kk0 = (kt & 7) * 16;
#pragma unroll
        for (int tt = 0; tt < 2; tt++) {
            int r = arow + tt * 64;
            int n = n0 + r;
            bool ok = n < NN;
            const float* src = srcb + (size_t)(ok ? n : 0) * H + kk0 + slot * 4;
            cp16p(&As[st][r * 16 + ((slot ^ ((r >> 1) & 3)) << 2)], src, ok);
        }
#pragma unroll
        for (int tt = 0; tt < 2; tt++) {
            int f4i = tid + tt * 256;
            int wr = f4i >> 5, wc = (f4i & 31) * 4;
            cp16(&Ws[st][wr * WS_STRIDE + wc],
                 W + (size_t)(kt * 16 + wr) * 128 + wc);
        }
    };

    load_tile(0, 0);
    CP_COMMIT();
    for (int t = 0; t < 104; t++) {
        if (t < 103) { load_tile(t + 1, (t + 1) & 1); CP_COMMIT(); CP_WAIT1(); }
        else CP_WAIT0();
        __syncthreads();
        mma_tile16(As[t & 1], Ws[t & 1], acc, lane, wm, wn);
        __syncthreads();
        if (t == 31) {           // acc = U3 -> scale by iamp^2
#pragma unroll
            for (int mt = 0; mt < 4; mt++)
#pragma unroll
                for (int nt = 0; nt < 4; nt++) {
                    acc[mt][nt][0] *= si2[mt * 2];     acc[mt][nt][1] *= si2[mt * 2];
                    acc[mt][nt][2] *= si2[mt * 2 + 1]; acc[mt][nt][3] *= si2[mt * 2 + 1];
                }
        } else if (t == 63) {    // acc = iamp^2*U3 + U2 -> scale by amp
#pragma unroll
            for (int mt = 0; mt < 4; mt++)
#pragma unroll
                for (int nt = 0; nt < 4; nt++) {
                    acc[mt][nt][0] *= sa[mt * 2];     acc[mt][nt][1] *= sa[mt * 2];
                    acc[mt][nt][2] *= sa[mt * 2 + 1]; acc[mt][nt][3] *= sa[mt * 2 + 1];
                }
        }
    }

#pragma unroll
    for (int mt = 0; mt < 4; mt++) {
        int r0 = n0 + wm * 64 + mt * 16 + (lane >> 2);
#pragma unroll
        for (int nt = 0; nt < 4; nt++) {
            int col = wn * 32 + nt * 8 + 2 * (lane & 3);
            float b0 = bias[col], b1 = bias[col + 1];
            if (r0 < NN)
                *(float2*)(g_tmp + (size_t)r0 * 128 + col) =
                    make_float2(acc[mt][nt][0] + b0, acc[mt][nt][1] + b1);
            if (r0 + 8 < NN)
                *(float2*)(g_tmp + (size_t)(r0 + 8) * 128 + col) =
                    make_float2(acc[mt][nt][2] + b0, acc[mt][nt][3] + b1);
        }
    }
}

// ---------------- sort / scan ----------------
__global__ void deg_count(const int* __restrict__ dstI) {
    int e = blockIdx.x * blockDim.x + threadIdx.x;
    if (e < NE) atomicAdd(&g_cnt[dstI[e]], 1);
}
__global__ __launch_bounds__(256) void scan1() {
    int b = blockIdx.x, t = threadIdx.x;
    int n = b * CHUNK + t;
    int v = (t < CHUNK && n < NN) ? g_cnt[n] : 0;
    int lane = t & 31, wid = t >> 5;
    int x = v;
#pragma unroll
    for (int off = 1; off < 32; off <<= 1) {
        int u = __shfl_up_sync(0xffffffffu, x, off);
        if (lane >= off) x += u;
    }
    __shared__ int wsum[8];
    if (lane == 31) wsum[wid] = x;
    __syncthreads();
    if (t == 0) {
        int r = 0;
#pragma unroll
        for (int i = 0; i < 8; i++) { int tmp = wsum[i]; wsum[i] = r; r += tmp; }
        g_part[b] = r;
    }
    __syncthreads();
    int excl = x - v + wsum[wid];
    if (t < CHUNK && n < NN) g_start[n] = excl;
}
__global__ void scan2() {
    int t = threadIdx.x;          // 128 threads
    int v = g_part[t];
    int lane = t & 31, wid = t >> 5;
    int x = v;
#pragma unroll
    for (int off = 1; off < 32; off <<= 1) {
        int u = __shfl_up_sync(0xffffffffu, x, off);
        if (lane >= off) x += u;
    }
    __shared__ int wsum[4];
    if (lane == 31) wsum[wid] = x;
    __syncthreads();
    if (t == 0) {
        int r = 0;
#pragma unroll
        for (int i = 0; i < 4; i++) { int tmp = wsum[i]; wsum[i] = r; r += tmp; }
    }
    __syncthreads();
    g_part[t] = x - v + wsum[wid];
}
__global__ void scan3() {
    int n = blockIdx.x * blockDim.x + threadIdx.x;
    if (n < NN) {
        int s = g_start[n] + g_part[n / CHUNK];
        g_start[n] = s;
        g_cursor[n] = s;
    }
    if (n == 0) g_start[NN] = NE;
}
__global__ void scatter_k(const int* __restrict__ srcI, const int* __restrict__ dstI) {
    int e = blockIdx.x * blockDim.x + threadIdx.x;
    if (e >= NE) return;
    int d = dstI[e];
    int p = atomicAdd(&g_cursor[d], 1);
    g_psrc[p] = srcI[e];
    g_pdst[p] = d;
    g_peid[p] = e;
}
__global__ void amp_k() {
    int n = blockIdx.x * blockDim.x + threadIdx.x;
    if (n >= NN) return;
    float degc = fmaxf((float)g_cnt[n], 1.f);
    float a = logf(degc + 1.f) / AVG_LOG;
    g_amp[n] = a;
    g_iamp[n] = 1.f / a;
}
__global__ void biasm_k(const float* __restrict__ be, const float* __restrict__ eb,
                        const float* __restrict__ P2, float* __restrict__ out,
                        const float* __restrict__ pb) {
    int j = threadIdx.x;
    float s = pb[j];
    for (int k = 0; k < 16; k++)  s += be[k] * g_T1[k * H + j];
    for (int k = 0; k < H; k++)   s += eb[k] * P2[k * H + j];
    out[j] = s;
}

// ---------------- BN / pool / head ----------------
__global__ void bn_stats() {
    int tid = threadIdx.x;
    int half = tid >> 7;
    float s = 0.f, q = 0.f;
    for (int row = blockIdx.x * 2 + half; row < NN; row += gridDim.x * 2) {
        float v = g_h2[(size_t)row * H + (tid & 127)];
        s += v; q += v * v;
    }
    __shared__ float sh[256];
    sh[tid] = s; __syncthreads();
    if (tid < 128) atomicAdd(&g_bn[tid], sh[tid] + sh[tid + 128]);
    __syncthreads();
    sh[tid] = q; __syncthreads();
    if (tid < 128) atomicAdd(&g_bn[128 + tid], sh[tid] + sh[tid + 128]);
}
__global__ void bn_norm(const float* __restrict__ gamma, const float* __restrict__ beta) {
    int idx = blockIdx.x * blockDim.x + threadIdx.x;
    if (idx >= NN * H) return;
    int c = idx & 127;
    const float invN = 1.f / (float)NN;
    float mu = g_bn[c] * invN;
    float var = g_bn[128 + c] * invN - mu * mu;
    float y = (g_h2[idx] - mu) * rsqrtf(var + EPS_BN) * gamma[c] + beta[c];
    g_h[idx] = fmaxf(y, 0.f);
}
__global__ void pool_k(const int* __restrict__ batch) {
    int c = threadIdx.x;
    int start = blockIdx.x * 256;
    int end = min(start + 256, NN);
    if (start >= NN) return;
    float acc = 0.f;
    int cur = batch[start];
    for (int n = start; n < end; n++) {
        int g = batch[n];
        if (g != cur) { atomicAdd(&g_pool[cur * H + c], acc); acc = 0.f; cur = g; }
        acc += g_h[(size_t)n * H + c];
    }
    atomicAdd(&g_pool[cur * H + c], acc);
}
__global__ void head1_k(const float* __restrict__ W1, const float* __restrict__ b1) {
    int idx = blockIdx.x * blockDim.x + threadIdx.x;
    if (idx >= NGR * 64) return;
    int g = idx >> 6, j = idx & 63;
    float s = b1[j];
    for (int k = 0; k < H; k++) s += g_pool[g * H + k] * W1[k * 64 + j];
    g_z[idx] = fmaxf(s, 0.f);
}
__global__ void head2_k(const float* __restrict__ W2, const float* __restrict__ b2,
                        float* __restrict__ out) {
    int idx = blockIdx.x * blockDim.x + threadIdx.x;
    if (idx >= NGR * NOUT) return;
    int g = idx / NOUT, j = idx % NOUT;
    float s = b2[j];
    for (int k = 0; k < 64; k++) s += g_z[g * 64 + k] * W2[k * NOUT + j];
    out[idx] = s;
}

// ---------------- launch ----------------
extern "C" void kernel_launch(void* const* d_in, const int* in_sizes, int n_in,
                              void* d_out, int out_size)
{
    int iEI = 1, iBatch = 2, iEA = 3;
    if (in_sizes[1] == NE * 16) { iEA = 1; iEI = 2; iBatch = 3; }

    const float* x         = (const float*)d_in[0];
    const int*   edge_index= (const int*)  d_in[iEI];
    const int*   batch     = (const int*)  d_in[iBatch];
    const float* edge_attr = (const float*)d_in[iEA];
    const float* node_emb_W= (const float*)d_in[4];
    const float* node_emb_b= (const float*)d_in[5];
    const float* edge_emb_W= (const float*)d_in[6];
    const float* edge_emb_b= (const float*)d_in[7];
    const float* edge_enc_W= (const float*)d_in[8];
    const float* edge_enc_b= (const float*)d_in[9];
    const float* pre_W     = (const float*)d_in[10];
    const float* pre_b     = (const float*)d_in[11];
    const float* post_W    = (const float*)d_in[12];
    const float* post_b    = (const float*)d_in[13];
    const float* lin_W     = (const float*)d_in[14];
    const float* lin_b     = (const float*)d_in[15];
    const float* bn_gamma  = (const float*)d_in[16];
    const float* bn_beta   = (const float*)d_in[17];
    const float* head1_W   = (const float*)d_in[18];
    const float* head1_b   = (const float*)d_in[19];
    const float* head2_W   = (const float*)d_in[20];
    const float* head2_b   = (const float*)d_in[21];

    const int* srcI = edge_index;
    const int* dstI = edge_index + NE;

    float *p_h, *p_h2, *p_tmp, *p_wcat, *p_T1, *p_biasm, *p_bn, *p_pool;
    int *p_cnt, *p_bcnt;
    cudaGetSymbolAddress((void**)&p_h,     g_h);
    cudaGetSymbolAddress((void**)&p_h2,    g_h2);
    cudaGetSymbolAddress((void**)&p_tmp,   g_tmp);
    cudaGetSymbolAddress((void**)&p_wcat,  g_WcatL);
    cudaGetSymbolAddress((void**)&p_T1,    g_T1);
    cudaGetSymbolAddress((void**)&p_biasm, g_biasmL);
    cudaGetSymbolAddress((void**)&p_bn,    g_bn);
    cudaGetSymbolAddress((void**)&p_pool,  g_pool);
    cudaGetSymbolAddress((void**)&p_cnt,   g_cnt);
    cudaGetSymbolAddress((void**)&p_bcnt,  g_bcnt);

    cudaFuncSetAttribute(edge_agg, cudaFuncAttributeMaxDynamicSharedMemorySize, EDGE_SMEM);

    // sort prep (memsets are graph nodes, not kernels)
    cudaMemsetAsync(p_cnt, 0, NN * sizeof(int));
    cudaMemsetAsync(p_bcnt, 0, sizeof(int));
    deg_count<<<(NE + 255) / 256, 256>>>(dstI);
    scan1<<<SCAN_B, 256>>>();
    scan2<<<1, 128>>>();
    gemm128t<<<(NN + 127) / 128, 256>>>(x, node_emb_W, node_emb_b, p_h, NN, 64);
    scan3<<<(NN + 255) / 256, 256>>>();
    scatter_k<<<(NE + 255) / 256, 256>>>(srcI, dstI);
    amp_k<<<(NN + 255) / 256, 256>>>();
    bnd_build<<<(NN + 255) / 256, 256>>>();

    // weight prep for all layers
    for (int l = 0; l < NL; l++) {
        const float* preWl = pre_W + (size_t)l * 384 * H;
        const float* P2 = preWl + 256 * H;
        float* wcat_l = p_wcat + (size_t)l * KCAT * H;
        cudaMemcpyAsync(wcat_l, preWl, 256 * H * sizeof(float), cudaMemcpyDeviceToDevice);
        gemm128<<<1, 256>>>(edge_enc_W + (size_t)l * H * H, P2,
                            (const float*)nullptr, p_T1, 128, 128);
        gemm128<<<1, 256>>>(edge_emb_W, p_T1,
                            (const float*)nullptr, wcat_l + 256 * H, 16, 128);
        biasm_k<<<1, 128>>>(edge_emb_b, edge_enc_b + l * H, P2,
                            p_biasm + l * H, pre_b + l * H);
    }

    for (int l = 0; l < NL; l++) {
        init_bnd<<<64, 256>>>();
        edge_agg<<<NE / 128, 256, EDGE_SMEM>>>(edge_attr,
                                               p_wcat + (size_t)l * KCAT * H,
                                               p_biasm + l * H);
        fin_bnd<<<64, 256>>>();

        post_gemmt<<<(NN + 127) / 128, 256>>>(post_W + (size_t)l * 13 * H * H, post_b + l * H);
        gemm128t<<<(NN + 127) / 128, 256>>>(p_tmp, lin_W + (size_t)l * H * H,
                                            lin_b + l * H, p_h2, NN, H);

        cudaMemsetAsync(p_bn, 0, 2 * H * sizeof(float));
        bn_stats<<<128, 256>>>();
        bn_norm<<<(NN * H + 255) / 256, 256>>>(bn_gamma + l * H, bn_beta + l * H);
    }

    cudaMemsetAsync(p_pool, 0, NGR * H * sizeof(float));
    pool_k<<<(NN + 255) / 256, 128>>>(batch);
    head1_k<<<8, 256>>>(head1_W, head1_b);
    head2_k<<<2, 256>>>(head2_W, head2_b, (float*)d_out);
}

// round 6
// speedup vs baseline: 4.9752x; 1.1085x over previous
#include <cuda_runtime.h>
#include <math.h>

#define NN 30000
#define NE 480000
#define H 128
#define NL 4
#define NGR 32
#define NOUT 12
#define AVG_LOG 1.38214548f
#define EPS_BN 1e-5f
#define EPS_STD 1e-5f
#define KCAT 272
#define WS_STRIDE 136
#define SCAN_B 128
#define CHUNK 235           // ceil(NN/SCAN_B)
#define BIG_SMEM 67584      // 16896 floats: A 2x4096 + W 2x4352 ; also >= 128*132*4

// ---------------- scratch ----------------
__device__ float g_h[NN * H];
__device__ float g_h2[NN * H];
__device__ float g_tmp[NN * H];
__device__ float g_mean[NN * H];
__device__ float g_std[NN * H];
__device__ float g_mn[NN * H];
__device__ float g_mx[NN * H];
__device__ float g_bsum[NN * H];
__device__ float g_bsq[NN * H];
__device__ float g_bmn[NN * H];
__device__ float g_bmx[NN * H];
__device__ int   g_cnt[NN];
__device__ int   g_start[NN + 1];
__device__ int   g_cursor[NN];
__device__ int   g_part[SCAN_B];
__device__ int   g_psrc[NE];
__device__ int   g_pdst[NE];
__device__ int   g_peid[NE];
__device__ int   g_blist[NN];
__device__ int   g_bcnt;
__device__ float g_amp[NN];
__device__ float g_iamp[NN];
__device__ float g_WcatL[NL * KCAT * H];
__device__ float g_T1[H * H];
__device__ float g_biasmL[NL * H];
__device__ float g_bn[2 * H];
__device__ float g_pool[NGR * H];
__device__ float g_z[NGR * 64];

// ---------------- helpers ----------------
__device__ __forceinline__ void atomicMaxF(float* a, float v) {
    if (v >= 0.f) atomicMax((int*)a, __float_as_int(v));
    else          atomicMin((unsigned int*)a, __float_as_uint(v));
}
__device__ __forceinline__ void atomicMinF(float* a, float v) {
    if (v >= 0.f) atomicMin((int*)a, __float_as_int(v));
    else          atomicMax((unsigned int*)a, __float_as_uint(v));
}
__device__ __forceinline__ void cp16(float* smem, const float* g) {
    unsigned sa = (unsigned)__cvta_generic_to_shared(smem);
    asm volatile("cp.async.cg.shared.global [%0], [%1], 16;\n" :: "r"(sa), "l"(g));
}
__device__ __forceinline__ void cp16p(float* smem, const float* g, bool pred) {
    unsigned sa = (unsigned)__cvta_generic_to_shared(smem);
    int sz = pred ? 16 : 0;
    asm volatile("cp.async.cg.shared.global [%0], [%1], 16, %2;\n" :: "r"(sa), "l"(g), "r"(sz));
}
#define CP_COMMIT() asm volatile("cp.async.commit_group;\n" ::: "memory")
#define CP_WAIT1()  asm volatile("cp.async.wait_group 1;\n" ::: "memory")
#define CP_WAIT0()  asm volatile("cp.async.wait_group 0;\n" ::: "memory")

// post-GEMM sub-tile order: group3 (72..103), group2 (40..71), group01 (0..39)
__device__ __forceinline__ int map_kt(int t) {
    return (t < 32) ? 72 + t : (t < 64) ? 40 + (t - 32) : (t - 64);
}

// A sub-tile swizzle: float4 slot s of row r -> base[r*16 + ((s ^ ((r>>1)&3))<<2)]
__device__ __forceinline__ unsigned ld_as(const float* As, int r, int slot, int c) {
    return __float_as_uint(As[r * 16 + ((slot ^ ((r >> 1) & 3)) << 2) + c]);
}

__device__ __forceinline__ void mma_tile16(const float* As, const float* Ws,
                                           float (&acc)[4][4][4], int lane,
                                           int wm, int wn)
{
#pragma unroll
    for (int ks = 0; ks < 2; ks++) {
        unsigned b0[4], b1[4];
        int bk = ks * 8 + (lane & 3);
        int bn = wn * 32 + (lane >> 2);
#pragma unroll
        for (int nt = 0; nt < 4; nt++) {
            b0[nt] = __float_as_uint(Ws[bk * WS_STRIDE + bn + nt * 8]);
            b1[nt] = __float_as_uint(Ws[(bk + 4) * WS_STRIDE + bn + nt * 8]);
        }
#pragma unroll
        for (int mt = 0; mt < 4; mt++) {
            int r0 = wm * 64 + mt * 16 + (lane >> 2);
            int r1 = r0 + 8;
            int c = lane & 3;
            unsigned a0 = ld_as(As, r0, ks * 2,     c);
            unsigned a1 = ld_as(As, r1, ks * 2,     c);
            unsigned a2 = ld_as(As, r0, ks * 2 + 1, c);
            unsigned a3 = ld_as(As, r1, ks * 2 + 1, c);
#pragma unroll
            for (int nt = 0; nt < 4; nt++) {
                asm volatile(
                    "mma.sync.aligned.m16n8k8.row.col.f32.tf32.tf32.f32 "
                    "{%0,%1,%2,%3}, {%4,%5,%6,%7}, {%8,%9}, {%0,%1,%2,%3};"
                    : "+f"(acc[mt][nt][0]), "+f"(acc[mt][nt][1]),
                      "+f"(acc[mt][nt][2]), "+f"(acc[mt][nt][3])
                    : "r"(a0), "r"(a1), "r"(a2), "r"(a3),
                      "r"(b0[nt]), "r"(b1[nt]));
            }
        }
    }
}

// ---------------- fp32 tiled GEMM (weight-prep only) ----------------
__global__ __launch_bounds__(256) void gemm128(
    const float* __restrict__ A, const float* __restrict__ W,
    const float* __restrict__ bias, float* __restrict__ C, int M, int K)
{
    __shared__ float As[16 * 132];
    __shared__ float Ws[16 * 128];
    int tid = threadIdx.x;
    int m0 = blockIdx.x * 128;
    int trow = tid >> 4, tcol = tid & 15;
    int r8 = trow * 8, c8 = tcol * 8;
    int arow = tid >> 2;
    int ac4 = (tid & 3) * 4;

    float acc[8][8];
#pragma unroll
    for (int i = 0; i < 8; i++)
#pragma unroll
        for (int j = 0; j < 8; j++) acc[i][j] = 0.f;

    for (int k0 = 0; k0 < K; k0 += 16) {
#pragma unroll
        for (int t = 0; t < 2; t++) {
            int r = arow + t * 64;
            int gr = m0 + r;
            float4 v = make_float4(0.f, 0.f, 0.f, 0.f);
            if (gr < M) v = *(const float4*)(A + (size_t)gr * K + k0 + ac4);
            As[(ac4 + 0) * 132 + r] = v.x;
            As[(ac4 + 1) * 132 + r] = v.y;
            As[(ac4 + 2) * 132 + r] = v.z;
            As[(ac4 + 3) * 132 + r] = v.w;
        }
#pragma unroll
        for (int t = 0; t < 2; t++) {
            int f4i = tid + t * 256;
            int wr = f4i >> 5, wc = (f4i & 31) * 4;
            *(float4*)&Ws[wr * 128 + wc] = *(const float4*)(W + (size_t)(k0 + wr) * 128 + wc);
        }
        __syncthreads();
#pragma unroll
        for (int kk = 0; kk < 16; kk++) {
            float4 a0 = *(const float4*)&As[kk * 132 + r8];
            float4 a1 = *(const float4*)&As[kk * 132 + r8 + 4];
            float4 w0 = *(const float4*)&Ws[kk * 128 + c8];
            float4 w1 = *(const float4*)&Ws[kk * 128 + c8 + 4];
            float a[8] = {a0.x, a0.y, a0.z, a0.w, a1.x, a1.y, a1.z, a1.w};
            float w[8] = {w0.x, w0.y, w0.z, w0.w, w1.x, w1.y, w1.z, w1.w};
#pragma unroll
            for (int i = 0; i < 8; i++)
#pragma unroll
                for (int j = 0; j < 8; j++) acc[i][j] += a[i] * w[j];
        }
        __syncthreads();
    }

    float b[8];
#pragma unroll
    for (int j = 0; j < 8; j++) b[j] = bias ? bias[c8 + j] : 0.f;
#pragma unroll
    for (int i = 0; i < 8; i++) {
        int gr = m0 + r8 + i;
        if (gr < M) {
            float4 o0, o1;
            o0.x = acc[i][0] + b[0]; o0.y = acc[i][1] + b[1];
            o0.z = acc[i][2] + b[2]; o0.w = acc[i][3] + b[3];
            o1.x = acc[i][4] + b[4]; o1.y = acc[i][5] + b[5];
            o1.z = acc[i][6] + b[6]; o1.w = acc[i][7] + b[7];
            *(float4*)(C + (size_t)gr * 128 + c8) = o0;
            *(float4*)(C + (size_t)gr * 128 + c8 + 4) = o1;
        }
    }
}

// ---------------- tensor-core generic GEMM (emb) ----------------
__global__ __launch_bounds__(256) void gemm128t(
    const float* __restrict__ A, const float* __restrict__ W,
    const float* __restrict__ bias, float* __restrict__ C, int M, int K)
{
    __shared__ float As[128 * 16];
    __shared__ float Ws[16 * WS_STRIDE];
    int tid = threadIdx.x;
    int lane = tid & 31, warp = tid >> 5;
    int wm = warp >> 2, wn = warp & 3;
    int m0 = blockIdx.x * 128;
    int arow = tid >> 2;
    int slot = tid & 3;
    float4* As4 = (float4*)As;

    float acc[4][4][4];
#pragma unroll
    for (int a = 0; a < 4; a++)
#pragma unroll
        for (int b = 0; b < 4; b++)
#pragma unroll
            for (int c = 0; c < 4; c++) acc[a][b][c] = 0.f;

    for (int k0 = 0; k0 < K; k0 += 16) {
#pragma unroll
        for (int t = 0; t < 2; t++) {
            int r = arow + t * 64;
            int gr = m0 + r;
            float4 v = make_float4(0.f, 0.f, 0.f, 0.f);
            if (gr < M) v = *(const float4*)(A + (size_t)gr * K + k0 + slot * 4);
            As4[r * 4 + (slot ^ ((r >> 1) & 3))] = v;
        }
#pragma unroll
        for (int t = 0; t < 2; t++) {
            int f4i = tid + t * 256;
            int wr = f4i >> 5, wc = (f4i & 31) * 4;
            *(float4*)&Ws[wr * WS_STRIDE + wc] =
                *(const float4*)(W + (size_t)(k0 + wr) * 128 + wc);
        }
        __syncthreads();
        mma_tile16(As, Ws, acc, lane, wm, wn);
        __syncthreads();
    }

#pragma unroll
    for (int mt = 0; mt < 4; mt++) {
        int r0 = m0 + wm * 64 + mt * 16 + (lane >> 2);
#pragma unroll
        for (int nt = 0; nt < 4; nt++) {
            int col = wn * 32 + nt * 8 + 2 * (lane & 3);
            float b0 = bias ? bias[col] : 0.f;
            float b1 = bias ? bias[col + 1] : 0.f;
            if (r0 < M)
                *(float2*)(C + (size_t)r0 * 128 + col) =
                    make_float2(acc[mt][nt][0] + b0, acc[mt][nt][1] + b1);
            if (r0 + 8 < M)
                *(float2*)(C + (size_t)(r0 + 8) * 128 + col) =
                    make_float2(acc[mt][nt][2] + b0, acc[mt][nt][3] + b1);
        }
    }
}

// ---------------- lin GEMM with fused BN stats (M=NN, K=128) ----------------
__global__ __launch_bounds__(256) void gemm128t_bn(
    const float* __restrict__ A, const float* __restrict__ W,
    const float* __restrict__ bias, float* __restrict__ C)
{
    __shared__ float As[128 * 16];
    __shared__ float Ws[16 * WS_STRIDE];
    __shared__ float sbn[256];
    int tid = threadIdx.x;
    int lane = tid & 31, warp = tid >> 5;
    int wm = warp >> 2, wn = warp & 3;
    int m0 = blockIdx.x * 128;
    int arow = tid >> 2;
    int slot = tid & 3;
    float4* As4 = (float4*)As;
    sbn[tid] = 0.f;

    float acc[4][4][4];
#pragma unroll
    for (int a = 0; a < 4; a++)
#pragma unroll
        for (int b = 0; b < 4; b++)
#pragma unroll
            for (int c = 0; c < 4; c++) acc[a][b][c] = 0.f;

    for (int k0 = 0; k0 < 128; k0 += 16) {
#pragma unroll
        for (int t = 0; t < 2; t++) {
            int r = arow + t * 64;
            int gr = m0 + r;
            float4 v = make_float4(0.f, 0.f, 0.f, 0.f);
            if (gr < NN) v = *(const float4*)(A + (size_t)gr * 128 + k0 + slot * 4);
            As4[r * 4 + (slot ^ ((r >> 1) & 3))] = v;
        }
#pragma unroll
        for (int t = 0; t < 2; t++) {
            int f4i = tid + t * 256;
            int wr = f4i >> 5, wc = (f4i & 31) * 4;
            *(float4*)&Ws[wr * WS_STRIDE + wc] =
                *(const float4*)(W + (size_t)(k0 + wr) * 128 + wc);
        }
        __syncthreads();
        mma_tile16(As, Ws, acc, lane, wm, wn);
        __syncthreads();
    }

    float csum[4][2] = {}, csq[4][2] = {};
#pragma unroll
    for (int mt = 0; mt < 4; mt++) {
        int r0 = m0 + wm * 64 + mt * 16 + (lane >> 2);
#pragma unroll
        for (int nt = 0; nt < 4; nt++) {
            int col = wn * 32 + nt * 8 + 2 * (lane & 3);
            float b0 = bias[col], b1 = bias[col + 1];
            float v0 = acc[mt][nt][0] + b0, v1 = acc[mt][nt][1] + b1;
            float v2 = acc[mt][nt][2] + b0, v3 = acc[mt][nt][3] + b1;
            if (r0 < NN) {
                *(float2*)(C + (size_t)r0 * 128 + col) = make_float2(v0, v1);
                csum[nt][0] += v0; csq[nt][0] += v0 * v0;
                csum[nt][1] += v1; csq[nt][1] += v1 * v1;
            }
            if (r0 + 8 < NN) {
                *(float2*)(C + (size_t)(r0 + 8) * 128 + col) = make_float2(v2, v3);
                csum[nt][0] += v2; csq[nt][0] += v2 * v2;
                csum[nt][1] += v3; csq[nt][1] += v3 * v3;
            }
        }
    }
    // reduce over the 8 lanes with identical (lane&3)
#pragma unroll
    for (int nt = 0; nt < 4; nt++)
#pragma unroll
        for (int j = 0; j < 2; j++) {
            float s = csum[nt][j], q = csq[nt][j];
            s += __shfl_down_sync(0xffffffffu, s, 16);
            s += __shfl_down_sync(0xffffffffu, s, 8);
            s += __shfl_down_sync(0xffffffffu, s, 4);
            q += __shfl_down_sync(0xffffffffu, q, 16);
            q += __shfl_down_sync(0xffffffffu, q, 8);
            q += __shfl_down_sync(0xffffffffu, q, 4);
            if (lane < 4) {
                int col = wn * 32 + nt * 8 + 2 * lane + j;
                atomicAdd(&sbn[col], s);
                atomicAdd(&sbn[128 + col], q);
            }
        }
    __syncthreads();
    atomicAdd(&g_bn[tid & 255], sbn[tid]);
}

// ---------------- fused edge message GEMM + segmented aggregation (BK=32) ----------------
__global__ __launch_bounds__(256) void edge_agg(const float* __restrict__ edge_attr,
                                                const float* __restrict__ Wcat,
                                                const float* __restrict__ biasm)
{
    extern __shared__ float s_dyn[];
    // A: 2 stages x 2 subs x 2048 ; W: 2 stages x 2 subs x 2176 (after offset 8192)
    float* mt_ = s_dyn;           // m tile [128 x 132], reused after compute
    __shared__ int sdst[128], ssrc[128], seid[128];

    int tid = threadIdx.x;
    int lane = tid & 31, warp = tid >> 5;
    int wm = warp >> 2, wn = warp & 3;
    int e0 = blockIdx.x * 128;
    int arow = tid >> 2;
    int slot = tid & 3;

    if (tid < 128) {
        int p = e0 + tid;
        sdst[tid] = g_pdst[p];
        ssrc[tid] = g_psrc[p];
        seid[tid] = g_peid[p];
    }
    __syncthreads();

    float acc[4][4][4];
#pragma unroll
    for (int a = 0; a < 4; a++)
#pragma unroll
        for (int b = 0; b < 4; b++)
#pragma unroll
            for (int c = 0; c < 4; c++) acc[a][b][c] = 0.f;

    auto a_sub = [&](int st, int j) { return s_dyn + st * 4096 + j * 2048; };
    auto w_sub = [&](int st, int j) { return s_dyn + 8192 + st * 4352 + j * 2176; };

    auto load_sub = [&](int kt, int st, int j) {
        float* ab = a_sub(st, j);
        float* wb = w_sub(st, j);
#pragma unroll
        for (int t = 0; t < 2; t++) {
            int r = arow + t * 64;
            const float* src;
            if (kt < 8)       src = g_h + (size_t)sdst[r] * H + kt * 16 + slot * 4;
            else if (kt < 16) src = g_h + (size_t)ssrc[r] * H + (kt - 8) * 16 + slot * 4;
            else              src = edge_attr + (size_t)seid[r] * 16 + slot * 4;
            cp16(&ab[r * 16 + ((slot ^ ((r >> 1) & 3)) << 2)], src);
        }
#pragma unroll
        for (int t = 0; t < 2; t++) {
            int f4i = tid + t * 256;
            int wr = f4i >> 5, wc = (f4i & 31) * 4;
            cp16(&wb[wr * WS_STRIDE + wc], Wcat + (size_t)(kt * 16 + wr) * 128 + wc);
        }
    };

    load_sub(0, 0, 0); load_sub(1, 0, 1);
    CP_COMMIT();
    for (int p = 0; p < 9; p++) {          // pairs of 16-k sub-tiles; 17 subs total
        if (p < 8) {
            int st = (p + 1) & 1;
            load_sub(2 * p + 2, st, 0);
            if (2 * p + 3 < 17) load_sub(2 * p + 3, st, 1);
            CP_COMMIT(); CP_WAIT1();
        } else CP_WAIT0();
        __syncthreads();
        int st = p & 1;
        mma_tile16(a_sub(st, 0), w_sub(st, 0), acc, lane, wm, wn);
        if (2 * p + 1 < 17)
            mma_tile16(a_sub(st, 1), w_sub(st, 1), acc, lane, wm, wn);
        __syncthreads();
    }

    // write message tile (+bias) to SMEM
#pragma unroll
    for (int mt2 = 0; mt2 < 4; mt2++) {
        int r0 = wm * 64 + mt2 * 16 + (lane >> 2);
#pragma unroll
        for (int nt = 0; nt < 4; nt++) {
            int col = wn * 32 + nt * 8 + 2 * (lane & 3);
            float b0 = biasm[col], b1 = biasm[col + 1];
            *(float2*)&mt_[r0 * 132 + col] =
                make_float2(acc[mt2][nt][0] + b0, acc[mt2][nt][1] + b1);
            *(float2*)&mt_[(r0 + 8) * 132 + col] =
                make_float2(acc[mt2][nt][2] + b0, acc[mt2][nt][3] + b1);
        }
    }
    __syncthreads();

    // segmented reduce: interior nodes final, boundary nodes via atomics
    int c = tid & 127, g2 = tid >> 7;
    int nfirst = sdst[0], nlast = sdst[127];
    for (int n = nfirst + g2; n <= nlast; n += 2) {
        int s = g_start[n], e = g_start[n + 1];
        if (s == e) continue;
        int lo = max(s, e0), hi = min(e, e0 + 128);
        if (lo >= hi) continue;
        float sumv = 0.f, sq = 0.f, mn = INFINITY, mx = -INFINITY;
        for (int r = lo - e0; r < hi - e0; r++) {
            float v = mt_[r * 132 + c];
            sumv += v; sq += v * v;
            mn = fminf(mn, v); mx = fmaxf(mx, v);
        }
        size_t idx = (size_t)n * H + c;
        if (s >= e0 && e <= e0 + 128) {
            float degc = (float)(e - s);
            float inv = 1.f / degc;
            float mean = sumv * inv;
            float var = fmaxf(sq * inv - mean * mean, 0.f);
            g_mean[idx] = mean;
            g_std[idx] = sqrtf(var + EPS_STD);
            g_mn[idx] = mn;
            g_mx[idx] = mx;
        } else {
            atomicAdd(&g_bsum[idx], sumv);
            atomicAdd(&g_bsq[idx], sq);
            atomicMinF(&g_bmn[idx], mn);
            atomicMaxF(&g_bmx[idx], mx);
        }
    }
}

// ---------------- boundary helpers ----------------
__global__ void bnd_build() {
    int n = blockIdx.x * blockDim.x + threadIdx.x;
    if (n >= NN) return;
    int s = g_start[n], e = g_start[n + 1];
    bool bnd = (s == e) || ((s >> 7) != ((e - 1) >> 7));
    if (bnd) {
        int p = atomicAdd(&g_bcnt, 1);
        g_blist[p] = n;
    }
}
__global__ void init_bnd() {
    int B = g_bcnt;
    int total = B * 128;
    for (int i = blockIdx.x * blockDim.x + threadIdx.x; i < total;
         i += gridDim.x * blockDim.x) {
        int n = g_blist[i >> 7];
        int c = i & 127;
        size_t idx = (size_t)n * H + c;
        g_bsum[idx] = 0.f; g_bsq[idx] = 0.f;
        g_bmn[idx] = INFINITY; g_bmx[idx] = -INFINITY;
    }
}
__global__ void fin_bnd() {
    int B = g_bcnt;
    int total = B * 128;
    for (int i = blockIdx.x * blockDim.x + threadIdx.x; i < total;
         i += gridDim.x * blockDim.x) {
        int n = g_blist[i >> 7];
        int c = i & 127;
        size_t idx = (size_t)n * H + c;
        int cnt = g_start[n + 1] - g_start[n];
        if (cnt == 0) {
            g_mean[idx] = 0.f; g_std[idx] = sqrtf(EPS_STD);
            g_mn[idx] = 0.f; g_mx[idx] = 0.f;
        } else {
            float inv = 1.f / (float)cnt;
            float mean = g_bsum[idx] * inv;
            float var = fmaxf(g_bsq[idx] * inv - mean * mean, 0.f);
            g_mean[idx] = mean;
            g_std[idx] = sqrtf(var + EPS_STD);
            g_mn[idx] = g_bmn[idx];
            g_mx[idx] = g_bmx[idx];
        }
    }
}

// ---------------- post-NN gather-GEMM (BK=32, reordered scaling) ----------------
__global__ __launch_bounds__(256) void post_gemmt(const float* __restrict__ W,
                                                  const float* __restrict__ bias)
{
    extern __shared__ float s_dyn[];
    int tid = threadIdx.x;
    int lane = tid & 31, warp = tid >> 5;
    int wm = warp >> 2, wn = warp & 3;
    int n0 = blockIdx.x * 128;
    int arow = tid >> 2;
    int slot = tid & 3;

    float sa[8], si2[8];
#pragma unroll
    for (int mt = 0; mt < 4; mt++)
#pragma unroll
        for (int hh = 0; hh < 2; hh++) {
            int n = n0 + wm * 64 + mt * 16 + (lane >> 2) + hh * 8;
            if (n >= NN) n = NN - 1;
            float a = g_amp[n], ia = g_iamp[n];
            sa[mt * 2 + hh] = a;
            si2[mt * 2 + hh] = ia * ia;
        }

    float acc[4][4][4];
#pragma unroll
    for (int a = 0; a < 4; a++)
#pragma unroll
        for (int b = 0; b < 4; b++)
#pragma unroll
            for (int c = 0; c < 4; c++) acc[a][b][c] = 0.f;

    auto a_sub = [&](int st, int j) { return s_dyn + st * 4096 + j * 2048; };
    auto w_sub = [&](int st, int j) { return s_dyn + 8192 + st * 4352 + j * 2176; };

    auto load_sub = [&](int t, int st, int j) {
        int kt = map_kt(t);
        int b = kt >> 3;
        const float* srcb;
        if (b == 0) srcb = g_h;
        else {
            int a = (b - 1) & 3;
            srcb = (a == 0) ? g_mean : (a == 1) ? g_mn : (a == 2) ? g_mx : g_std;
        }
        int kk0 = (kt & 7) * 16;
        float* ab = a_sub(st, j);
        float* wb = w_sub(st, j);
#pragma unroll
        for (int tt = 0; tt < 2; tt++) {
            int r = arow + tt * 64;
            int n = n0 + r;
            bool ok = n < NN;
            const float* src = srcb + (size_t)(ok ? n : 0) * H + kk0 + slot * 4;
            cp16p(&ab[r * 16 + ((slot ^ ((r >> 1) & 3)) << 2)], src, ok);
        }
#pragma unroll
        for (int tt = 0; tt < 2; tt++) {
            int f4i = tid + tt * 256;
            int wr = f4i >> 5, wc = (f4i & 31) * 4;
            cp16(&wb[wr * WS_STRIDE + wc], W + (size_t)(kt * 16 + wr) * 128 + wc);
        }
    };

    load_sub(0, 0, 0); load_sub(1, 0, 1);
    CP_COMMIT();
    for (int p = 0; p < 52; p++) {         // 104 sub-tiles as 52 pairs
        if (p < 51) {
            int st = (p + 1) & 1;
            load_sub(2 * p + 2, st, 0);
            load_sub(2 * p + 3, st, 1);
            CP_COMMIT(); CP_WAIT1();
        } else CP_WAIT0();
        __syncthreads();
        int st = p & 1;
        mma_tile16(a_sub(st, 0), w_sub(st, 0), acc, lane, wm, wn);
        mma_tile16(a_sub(st, 1), w_sub(st, 1), acc, lane, wm, wn);
        __syncthreads();
        if (p == 15) {           // finished U3 (subtiles 0..31) -> scale by iamp^2
#pragma unroll
            for (int mt = 0; mt < 4; mt++)
#pragma unroll
                for (int nt = 0; nt < 4; nt++) {
                    acc[mt][nt][0] *= si2[mt * 2];     acc[mt][nt][1] *= si2[mt * 2];
                    acc[mt][nt][2] *= si2[mt * 2 + 1]; acc[mt][nt][3] *= si2[mt * 2 + 1];
                }
        } else if (p == 31) {    // finished U2 -> scale by amp
#pragma unroll
            for (int mt = 0; mt < 4; mt++)
#pragma unroll
                for (int nt = 0; nt < 4; nt++) {
                    acc[mt][nt][0] *= sa[mt * 2];     acc[mt][nt][1] *= sa[mt * 2];
                    acc[mt][nt][2] *= sa[mt * 2 + 1]; acc[mt][nt][3] *= sa[mt * 2 + 1];
                }
        }
    }

#pragma unroll
    for (int mt = 0; mt < 4; mt++) {
        int r0 = n0 + wm * 64 + mt * 16 + (lane >> 2);
#pragma unroll
        for (int nt = 0; nt < 4; nt++) {
            int col = wn * 32 + nt * 8 + 2 * (lane & 3);
            float b0 = bias[col], b1 = bias[col + 1];
            if (r0 < NN)
                *(float2*)(g_tmp + (size_t)r0 * 128 + col) =
                    make_float2(acc[mt][nt][0] + b0, acc[mt][nt][1] + b1);
            if (r0 + 8 < NN)
                *(float2*)(g_tmp + (size_t)(r0 + 8) * 128 + col) =
                    make_float2(acc[mt][nt][2] + b0, acc[mt][nt][3] + b1);
        }
    }
}

// ---------------- sort / scan ----------------
__global__ void deg_count(const int* __restrict__ dstI) {
    int e = blockIdx.x * blockDim.x + threadIdx.x;
    if (e < NE) atomicAdd(&g_cnt[dstI[e]], 1);
}
__global__ __launch_bounds__(256) void scan1() {
    int b = blockIdx.x, t = threadIdx.x;
    int n = b * CHUNK + t;
    int v = (t < CHUNK && n < NN) ? g_cnt[n] : 0;
    int lane = t & 31, wid = t >> 5;
    int x = v;
#pragma unroll
    for (int off = 1; off < 32; off <<= 1) {
        int u = __shfl_up_sync(0xffffffffu, x, off);
        if (lane >= off) x += u;
    }
    __shared__ int wsum[8];
    if (lane == 31) wsum[wid] = x;
    __syncthreads();
    if (t == 0) {
        int r = 0;
#pragma unroll
        for (int i = 0; i < 8; i++) { int tmp = wsum[i]; wsum[i] = r; r += tmp; }
        g_part[b] = r;
    }
    __syncthreads();
    int excl = x - v + wsum[wid];
    if (t < CHUNK && n < NN) g_start[n] = excl;
}
__global__ void scan2() {
    int t = threadIdx.x;          // 128 threads
    int v = g_part[t];
    int lane = t & 31, wid = t >> 5;
    int x = v;
#pragma unroll
    for (int off = 1; off < 32; off <<= 1) {
        int u = __shfl_up_sync(0xffffffffu, x, off);
        if (lane >= off) x += u;
    }
    __shared__ int wsum[4];
    if (lane == 31) wsum[wid] = x;
    __syncthreads();
    if (t == 0) {
        int r = 0;
#pragma unroll
        for (int i = 0; i < 4; i++) { int tmp = wsum[i]; wsum[i] = r; r += tmp; }
    }
    __syncthreads();
    g_part[t] = x - v + wsum[wid];
}
__global__ void scan3() {
    int n = blockIdx.x * blockDim.x + threadIdx.x;
    if (n < NN) {
        int s = g_start[n] + g_part[n / CHUNK];
        g_start[n] = s;
        g_cursor[n] = s;
    }
    if (n == 0) g_start[NN] = NE;
}
__global__ void scatter_k(const int* __restrict__ srcI, const int* __restrict__ dstI) {
    int e = blockIdx.x * blockDim.x + threadIdx.x;
    if (e >= NE) return;
    int d = dstI[e];
    int p = atomicAdd(&g_cursor[d], 1);
    g_psrc[p] = srcI[e];
    g_pdst[p] = d;
    g_peid[p] = e;
}
__global__ void amp_k() {
    int n = blockIdx.x * blockDim.x + threadIdx.x;
    if (n >= NN) return;
    float degc = fmaxf((float)g_cnt[n], 1.f);
    float a = logf(degc + 1.f) / AVG_LOG;
    g_amp[n] = a;
    g_iamp[n] = 1.f / a;
}
__global__ void biasm_k(const float* __restrict__ be, const float* __restrict__ eb,
                        const float* __restrict__ P2, float* __restrict__ out,
                        const float* __restrict__ pb) {
    int j = threadIdx.x;
    float s = pb[j];
    for (int k = 0; k < 16; k++)  s += be[k] * g_T1[k * H + j];
    for (int k = 0; k < H; k++)   s += eb[k] * P2[k * H + j];
    out[j] = s;
}

// ---------------- BN / pool / head ----------------
__global__ void bn_norm(const float* __restrict__ gamma, const float* __restrict__ beta) {
    int idx = blockIdx.x * blockDim.x + threadIdx.x;
    if (idx >= NN * H) return;
    int c = idx & 127;
    const float invN = 1.f / (float)NN;
    float mu = g_bn[c] * invN;
    float var = g_bn[128 + c] * invN - mu * mu;
    float y = (g_h2[idx] - mu) * rsqrtf(var + EPS_BN) * gamma[c] + beta[c];
    g_h[idx] = fmaxf(y, 0.f);
}
__global__ void pool_k(const int* __restrict__ batch) {
    int c = threadIdx.x;
    int start = blockIdx.x * 256;
    int end = min(start + 256, NN);
    if (start >= NN) return;
    float acc = 0.f;
    int cur = batch[start];
    for (int n = start; n < end; n++) {
        int g = batch[n];
        if (g != cur) { atomicAdd(&g_pool[cur * H + c], acc); acc = 0.f; cur = g; }
        acc += g_h[(size_t)n * H + c];
    }
    atomicAdd(&g_pool[cur * H + c], acc);
}
__global__ void head1_k(const float* __restrict__ W1, const float* __restrict__ b1) {
    int idx = blockIdx.x * blockDim.x + threadIdx.x;
    if (idx >= NGR * 64) return;
    int g = idx >> 6, j = idx & 63;
    float s = b1[j];
    for (int k = 0; k < H; k++) s += g_pool[g * H + k] * W1[k * 64 + j];
    g_z[idx] = fmaxf(s, 0.f);
}
__global__ void head2_k(const float* __restrict__ W2, const float* __restrict__ b2,
                        float* __restrict__ out) {
    int idx = blockIdx.x * blockDim.x + threadIdx.x;
    if (idx >= NGR * NOUT) return;
    int g = idx / NOUT, j = idx % NOUT;
    float s = b2[j];
    for (int k = 0; k < 64; k++) s += g_z[g * 64 + k] * W2[k * NOUT + j];
    out[idx] = s;
}

// ---------------- launch ----------------
extern "C" void kernel_launch(void* const* d_in, const int* in_sizes, int n_in,
                              void* d_out, int out_size)
{
    int iEI = 1, iBatch = 2, iEA = 3;
    if (in_sizes[1] == NE * 16) { iEA = 1; iEI = 2; iBatch = 3; }

    const float* x         = (const float*)d_in[0];
    const int*   edge_index= (const int*)  d_in[iEI];
    const int*   batch     = (const int*)  d_in[iBatch];
    const float* edge_attr = (const float*)d_in[iEA];
    const float* node_emb_W= (const float*)d_in[4];
    const float* node_emb_b= (const float*)d_in[5];
    const float* edge_emb_W= (const float*)d_in[6];
    const float* edge_emb_b= (const float*)d_in[7];
    const float* edge_enc_W= (const float*)d_in[8];
    const float* edge_enc_b= (const float*)d_in[9];
    const float* pre_W     = (const float*)d_in[10];
    const float* pre_b     = (const float*)d_in[11];
    const float* post_W    = (const float*)d_in[12];
    const float* post_b    = (const float*)d_in[13];
    const float* lin_W     = (const float*)d_in[14];
    const float* lin_b     = (const float*)d_in[15];
    const float* bn_gamma  = (const float*)d_in[16];
    const float* bn_beta   = (const float*)d_in[17];
    const float* head1_W   = (const float*)d_in[18];
    const float* head1_b   = (const float*)d_in[19];
    const float* head2_W   = (const float*)d_in[20];
    const float* head2_b   = (const float*)d_in[21];

    const int* srcI = edge_index;
    const int* dstI = edge_index + NE;

    float *p_h, *p_h2, *p_tmp, *p_wcat, *p_T1, *p_biasm, *p_bn, *p_pool;
    int *p_cnt, *p_bcnt;
    cudaGetSymbolAddress((void**)&p_h,     g_h);
    cudaGetSymbolAddress((void**)&p_h2,    g_h2);
    cudaGetSymbolAddress((void**)&p_tmp,   g_tmp);
    cudaGetSymbolAddress((void**)&p_wcat,  g_WcatL);
    cudaGetSymbolAddress((void**)&p_T1,    g_T1);
    cudaGetSymbolAddress((void**)&p_biasm, g_biasmL);
    cudaGetSymbolAddress((void**)&p_bn,    g_bn);
    cudaGetSymbolAddress((void**)&p_pool,  g_pool);
    cudaGetSymbolAddress((void**)&p_cnt,   g_cnt);
    cudaGetSymbolAddress((void**)&p_bcnt,  g_bcnt);

    cudaFuncSetAttribute(edge_agg, cudaFuncAttributeMaxDynamicSharedMemorySize, BIG_SMEM);
    cudaFuncSetAttribute(post_gemmt, cudaFuncAttributeMaxDynamicSharedMemorySize, BIG_SMEM);

    // sort prep
    cudaMemsetAsync(p_cnt, 0, NN * sizeof(int));
    cudaMemsetAsync(p_bcnt, 0, sizeof(int));
    deg_count<<<(NE + 255) / 256, 256>>>(dstI);
    scan1<<<SCAN_B, 256>>>();
    scan2<<<1, 128>>>();
    gemm128t<<<(NN + 127) / 128, 256>>>(x, node_emb_W, node_emb_b, p_h, NN, 64);
    scan3<<<(NN + 255) / 256, 256>>>();
    scatter_k<<<(NE + 255) / 256, 256>>>(srcI, dstI);
    amp_k<<<(NN + 255) / 256, 256>>>();
    bnd_build<<<(NN + 255) / 256, 256>>>();

    // weight prep for all layers
    for (int l = 0; l < NL; l++) {
        const float* preWl = pre_W + (size_t)l * 384 * H;
        const float* P2 = preWl + 256 * H;
        float* wcat_l = p_wcat + (size_t)l * KCAT * H;
        cudaMemcpyAsync(wcat_l, preWl, 256 * H * sizeof(float), cudaMemcpyDeviceToDevice);
        gemm128<<<1, 256>>>(edge_enc_W + (size_t)l * H * H, P2,
                            (const float*)nullptr, p_T1, 128, 128);
        gemm128<<<1, 256>>>(edge_emb_W, p_T1,
                            (const float*)nullptr, wcat_l + 256 * H, 16, 128);
        biasm_k<<<1, 128>>>(edge_emb_b, edge_enc_b + l * H, P2,
                            p_biasm + l * H, pre_b + l * H);
    }

    for (int l = 0; l < NL; l++) {
        init_bnd<<<64, 256>>>();
        edge_agg<<<NE / 128, 256, BIG_SMEM>>>(edge_attr,
                                              p_wcat + (size_t)l * KCAT * H,
                                              p_biasm + l * H);
        fin_bnd<<<64, 256>>>();

        post_gemmt<<<(NN + 127) / 128, 256, BIG_SMEM>>>(
            post_W + (size_t)l * 13 * H * H, post_b + l * H);

        cudaMemsetAsync(p_bn, 0, 2 * H * sizeof(float));
        gemm128t_bn<<<(NN + 127) / 128, 256>>>(p_tmp, lin_W + (size_t)l * H * H,
                                               lin_b + l * H, p_h2);
        bn_norm<<<(NN * H + 255) / 256, 256>>>(bn_gamma + l * H, bn_beta + l * H);
    }

    cudaMemsetAsync(p_pool, 0, NGR * H * sizeof(float));
    pool_k<<<(NN + 255) / 256, 128>>>(batch);
    head1_k<<<8, 256>>>(head1_W, head1_b);
    head2_k<<<2, 256>>>(head2_W, head2_b, (float*)d_out);
}

// round 7
// speedup vs baseline: 6.6984x; 1.3463x over previous
#include <cuda_runtime.h>
#include <cuda_fp16.h>
#include <math.h>

#define NN 30000
#define NE 480000
#define H 128
#define NL 4
#define NGR 32
#define NOUT 12
#define AVG_LOG 1.38214548f
#define EPS_BN 1e-5f
#define EPS_STD 1e-5f
#define KCAT 272
#define KP_EDGE 144        // padded kpairs for Wcat (272->288 k)
#define KP_POST 832        // 1664 k
#define KP_LIN 64          // 128 k
#define WS_STRIDE 136
#define SCAN_B 128
#define CHUNK 235
#define BIG_SMEM 67584     // bytes; = 16896 words: A 2st*2sub*2048 + W 2st*2sub*2176

// ---------------- scratch ----------------
__device__ float g_h[NN * H];
__device__ float g_h2[NN * H];
__device__ __half g_h16[NN * H];
__device__ __half g_tmp16[NN * H];
__device__ __half g_mean16[NN * H];
__device__ __half g_std16[NN * H];
__device__ __half g_mn16[NN * H];
__device__ __half g_mx16[NN * H];
__device__ __half g_ea16[NE * 32];
__device__ float g_bsum[NN * H];
__device__ float g_bsq[NN * H];
__device__ float g_bmn[NN * H];
__device__ float g_bmx[NN * H];
__device__ int   g_cnt[NN];
__device__ int   g_start[NN + 1];
__device__ int   g_cursor[NN];
__device__ int   g_part[SCAN_B];
__device__ int   g_psrc[NE];
__device__ int   g_pdst[NE];
__device__ int   g_peid[NE];
__device__ int   g_blist[NN];
__device__ int   g_bcnt;
__device__ float g_amp[NN];
__device__ float g_iamp[NN];
__device__ float g_WcatL[NL * KCAT * H];
__device__ unsigned g_WcatH[NL * KP_EDGE * H];
__device__ unsigned g_postWH[NL * KP_POST * H];
__device__ unsigned g_linWH[NL * KP_LIN * H];
__device__ float g_T1[H * H];
__device__ float g_biasmL[NL * H];
__device__ float g_bn[2 * H];
__device__ float g_pool[NGR * H];
__device__ float g_z[NGR * 64];

// ---------------- helpers ----------------
__device__ __forceinline__ void atomicMaxF(float* a, float v) {
    if (v >= 0.f) atomicMax((int*)a, __float_as_int(v));
    else          atomicMin((unsigned int*)a, __float_as_uint(v));
}
__device__ __forceinline__ void atomicMinF(float* a, float v) {
    if (v >= 0.f) atomicMin((int*)a, __float_as_int(v));
    else          atomicMax((unsigned int*)a, __float_as_uint(v));
}
__device__ __forceinline__ void cp16(void* smem, const void* g) {
    unsigned sa = (unsigned)__cvta_generic_to_shared(smem);
    asm volatile("cp.async.cg.shared.global [%0], [%1], 16;\n" :: "r"(sa), "l"(g));
}
#define CP_COMMIT() asm volatile("cp.async.commit_group;\n" ::: "memory")
#define CP_WAIT1()  asm volatile("cp.async.wait_group 1;\n" ::: "memory")
#define CP_WAIT0()  asm volatile("cp.async.wait_group 0;\n" ::: "memory")

// post 32-k tile order: group3 (36..51), group2 (20..35), group01 (0..19)
__device__ __forceinline__ int map_t32(int t) {
    return (t < 16) ? 36 + t : (t < 32) ? 20 + (t - 16) : (t - 32);
}

// A tile: 128 rows x 16 half2 (32 k). slot s (4 half2) of row r at (s ^ ((r>>1)&3)).
__device__ __forceinline__ unsigned ld_a(const unsigned* As, int r, int slot, int c) {
    return As[r * 16 + ((slot ^ ((r >> 1) & 3)) << 2) + c];
}

// fp16 mma over one 32-k tile. As: [128][16] half2 swizzled; Ws: [16 kpairs][WS_STRIDE] half2.
__device__ __forceinline__ void mma_tile32(const unsigned* As, const unsigned* Ws,
                                           float (&acc)[4][4][4], int lane,
                                           int wm, int wn)
{
#pragma unroll
    for (int ks = 0; ks < 2; ks++) {
        unsigned b0[4], b1[4];
        int bk = ks * 8 + (lane & 3);
        int bn = wn * 32 + (lane >> 2);
#pragma unroll
        for (int nt = 0; nt < 4; nt++) {
            b0[nt] = Ws[bk * WS_STRIDE + bn + nt * 8];
            b1[nt] = Ws[(bk + 4) * WS_STRIDE + bn + nt * 8];
        }
#pragma unroll
        for (int mt = 0; mt < 4; mt++) {
            int r0 = wm * 64 + mt * 16 + (lane >> 2);
            int r1 = r0 + 8;
            int c = lane & 3;
            unsigned a0 = ld_a(As, r0, ks * 2,     c);
            unsigned a1 = ld_a(As, r1, ks * 2,     c);
            unsigned a2 = ld_a(As, r0, ks * 2 + 1, c);
            unsigned a3 = ld_a(As, r1, ks * 2 + 1, c);
#pragma unroll
            for (int nt = 0; nt < 4; nt++) {
                asm volatile(
                    "mma.sync.aligned.m16n8k16.row.col.f32.f16.f16.f32 "
                    "{%0,%1,%2,%3}, {%4,%5,%6,%7}, {%8,%9}, {%0,%1,%2,%3};"
                    : "+f"(acc[mt][nt][0]), "+f"(acc[mt][nt][1]),
                      "+f"(acc[mt][nt][2]), "+f"(acc[mt][nt][3])
                    : "r"(a0), "r"(a1), "r"(a2), "r"(a3),
                      "r"(b0[nt]), "r"(b1[nt]));
            }
        }
    }
}

// ---------------- tf32 path kept for emb GEMM (fp32 A) ----------------
__device__ __forceinline__ unsigned ld_asf(const float* As, int r, int slot, int c) {
    return __float_as_uint(As[r * 16 + ((slot ^ ((r >> 1) & 3)) << 2) + c]);
}
__device__ __forceinline__ void mma_tile16f(const float* As, const float* Ws,
                                            float (&acc)[4][4][4], int lane,
                                            int wm, int wn)
{
#pragma unroll
    for (int ks = 0; ks < 2; ks++) {
        unsigned b0[4], b1[4];
        int bk = ks * 8 + (lane & 3);
        int bn = wn * 32 + (lane >> 2);
#pragma unroll
        for (int nt = 0; nt < 4; nt++) {
            b0[nt] = __float_as_uint(Ws[bk * WS_STRIDE + bn + nt * 8]);
            b1[nt] = __float_as_uint(Ws[(bk + 4) * WS_STRIDE + bn + nt * 8]);
        }
#pragma unroll
        for (int mt = 0; mt < 4; mt++) {
            int r0 = wm * 64 + mt * 16 + (lane >> 2);
            int r1 = r0 + 8;
            int c = lane & 3;
            unsigned a0 = ld_asf(As, r0, ks * 2,     c);
            unsigned a1 = ld_asf(As, r1, ks * 2,     c);
            unsigned a2 = ld_asf(As, r0, ks * 2 + 1, c);
            unsigned a3 = ld_asf(As, r1, ks * 2 + 1, c);
#pragma unroll
            for (int nt = 0; nt < 4; nt++) {
                asm volatile(
                    "mma.sync.aligned.m16n8k8.row.col.f32.tf32.tf32.f32 "
                    "{%0,%1,%2,%3}, {%4,%5,%6,%7}, {%8,%9}, {%0,%1,%2,%3};"
                    : "+f"(acc[mt][nt][0]), "+f"(acc[mt][nt][1]),
                      "+f"(acc[mt][nt][2]), "+f"(acc[mt][nt][3])
                    : "r"(a0), "r"(a1), "r"(a2), "r"(a3),
                      "r"(b0[nt]), "r"(b1[nt]));
            }
        }
    }
}

// ---------------- fp32 tiled GEMM (weight prep only) ----------------
__global__ __launch_bounds__(256) void gemm128(
    const float* __restrict__ A, const float* __restrict__ W,
    const float* __restrict__ bias, float* __restrict__ C, int M, int K)
{
    __shared__ float As[16 * 132];
    __shared__ float Ws[16 * 128];
    int tid = threadIdx.x;
    int m0 = blockIdx.x * 128;
    int trow = tid >> 4, tcol = tid & 15;
    int r8 = trow * 8, c8 = tcol * 8;
    int arow = tid >> 2;
    int ac4 = (tid & 3) * 4;

    float acc[8][8];
#pragma unroll
    for (int i = 0; i < 8; i++)
#pragma unroll
        for (int j = 0; j < 8; j++) acc[i][j] = 0.f;

    for (int k0 = 0; k0 < K; k0 += 16) {
#pragma unroll
        for (int t = 0; t < 2; t++) {
            int r = arow + t * 64;
            int gr = m0 + r;
            float4 v = make_float4(0.f, 0.f, 0.f, 0.f);
            if (gr < M) v = *(const float4*)(A + (size_t)gr * K + k0 + ac4);
            As[(ac4 + 0) * 132 + r] = v.x;
            As[(ac4 + 1) * 132 + r] = v.y;
            As[(ac4 + 2) * 132 + r] = v.z;
            As[(ac4 + 3) * 132 + r] = v.w;
        }
#pragma unroll
        for (int t = 0; t < 2; t++) {
            int f4i = tid + t * 256;
            int wr = f4i >> 5, wc = (f4i & 31) * 4;
            *(float4*)&Ws[wr * 128 + wc] = *(const float4*)(W + (size_t)(k0 + wr) * 128 + wc);
        }
        __syncthreads();
#pragma unroll
        for (int kk = 0; kk < 16; kk++) {
            float4 a0 = *(const float4*)&As[kk * 132 + r8];
            float4 a1 = *(const float4*)&As[kk * 132 + r8 + 4];
            float4 w0 = *(const float4*)&Ws[kk * 128 + c8];
            float4 w1 = *(const float4*)&Ws[kk * 128 + c8 + 4];
            float a[8] = {a0.x, a0.y, a0.z, a0.w, a1.x, a1.y, a1.z, a1.w};
            float w[8] = {w0.x, w0.y, w0.z, w0.w, w1.x, w1.y, w1.z, w1.w};
#pragma unroll
            for (int i = 0; i < 8; i++)
#pragma unroll
                for (int j = 0; j < 8; j++) acc[i][j] += a[i] * w[j];
        }
        __syncthreads();
    }

    float b[8];
#pragma unroll
    for (int j = 0; j < 8; j++) b[j] = bias ? bias[c8 + j] : 0.f;
#pragma unroll
    for (int i = 0; i < 8; i++) {
        int gr = m0 + r8 + i;
        if (gr < M) {
            float4 o0, o1;
            o0.x = acc[i][0] + b[0]; o0.y = acc[i][1] + b[1];
            o0.z = acc[i][2] + b[2]; o0.w = acc[i][3] + b[3];
            o1.x = acc[i][4] + b[4]; o1.y = acc[i][5] + b[5];
            o1.z = acc[i][6] + b[6]; o1.w = acc[i][7] + b[7];
            *(float4*)(C + (size_t)gr * 128 + c8) = o0;
            *(float4*)(C + (size_t)gr * 128 + c8 + 4) = o1;
        }
    }
}

// ---------------- emb GEMM (tf32): writes fp32 h + fp16 h ----------------
__global__ __launch_bounds__(256) void emb_gemmt(
    const float* __restrict__ A, const float* __restrict__ W,
    const float* __restrict__ bias, int K)
{
    __shared__ float As[128 * 16];
    __shared__ float Ws[16 * WS_STRIDE];
    int tid = threadIdx.x;
    int lane = tid & 31, warp = tid >> 5;
    int wm = warp >> 2, wn = warp & 3;
    int m0 = blockIdx.x * 128;
    int arow = tid >> 2;
    int slot = tid & 3;
    float4* As4 = (float4*)As;

    float acc[4][4][4];
#pragma unroll
    for (int a = 0; a < 4; a++)
#pragma unroll
        for (int b = 0; b < 4; b++)
#pragma unroll
            for (int c = 0; c < 4; c++) acc[a][b][c] = 0.f;

    for (int k0 = 0; k0 < K; k0 += 16) {
#pragma unroll
        for (int t = 0; t < 2; t++) {
            int r = arow + t * 64;
            int gr = m0 + r;
            float4 v = make_float4(0.f, 0.f, 0.f, 0.f);
            if (gr < NN) v = *(const float4*)(A + (size_t)gr * K + k0 + slot * 4);
            As4[r * 4 + (slot ^ ((r >> 1) & 3))] = v;
        }
#pragma unroll
        for (int t = 0; t < 2; t++) {
            int f4i = tid + t * 256;
            int wr = f4i >> 5, wc = (f4i & 31) * 4;
            *(float4*)&Ws[wr * WS_STRIDE + wc] =
                *(const float4*)(W + (size_t)(k0 + wr) * 128 + wc);
        }
        __syncthreads();
        mma_tile16f(As, Ws, acc, lane, wm, wn);
        __syncthreads();
    }

#pragma unroll
    for (int mt = 0; mt < 4; mt++) {
        int r0 = m0 + wm * 64 + mt * 16 + (lane >> 2);
#pragma unroll
        for (int nt = 0; nt < 4; nt++) {
            int col = wn * 32 + nt * 8 + 2 * (lane & 3);
            float b0 = bias[col], b1 = bias[col + 1];
            float v0 = acc[mt][nt][0] + b0, v1 = acc[mt][nt][1] + b1;
            float v2 = acc[mt][nt][2] + b0, v3 = acc[mt][nt][3] + b1;
            if (r0 < NN) {
                *(float2*)(g_h + (size_t)r0 * 128 + col) = make_float2(v0, v1);
                __half2 hv = __floats2half2_rn(v0, v1);
                *(__half2*)(g_h16 + (size_t)r0 * 128 + col) = hv;
            }
            if (r0 + 8 < NN) {
                *(float2*)(g_h + (size_t)(r0 + 8) * 128 + col) = make_float2(v2, v3);
                __half2 hv = __floats2half2_rn(v2, v3);
                *(__half2*)(g_h16 + (size_t)(r0 + 8) * 128 + col) = hv;
            }
        }
    }
}

// ---------------- lin GEMM fp16 with fused BN stats (K=128) ----------------
__global__ __launch_bounds__(256) void lin_gemm_bn(
    const unsigned* __restrict__ Wp, const float* __restrict__ bias)
{
    __shared__ unsigned As2[128 * 16];       // 32-k tile of half2
    __shared__ unsigned Ws2[16 * WS_STRIDE];
    __shared__ float sbn[256];
    int tid = threadIdx.x;
    int lane = tid & 31, warp = tid >> 5;
    int wm = warp >> 2, wn = warp & 3;
    int m0 = blockIdx.x * 128;
    int arow = tid >> 2;
    int slot = tid & 3;
    uint4* As4 = (uint4*)As2;
    sbn[tid] = 0.f;

    float acc[4][4][4];
#pragma unroll
    for (int a = 0; a < 4; a++)
#pragma unroll
        for (int b = 0; b < 4; b++)
#pragma unroll
            for (int c = 0; c < 4; c++) acc[a][b][c] = 0.f;

    for (int kt = 0; kt < 4; kt++) {         // 4 tiles of 32 k
#pragma unroll
        for (int t = 0; t < 2; t++) {
            int r = arow + t * 64;
            int gr = m0 + r;
            uint4 v = make_uint4(0, 0, 0, 0);
            if (gr < NN)
                v = *(const uint4*)(g_tmp16 + (size_t)gr * 128 + kt * 32 + slot * 8);
            As4[r * 4 + (slot ^ ((r >> 1) & 3))] = v;
        }
#pragma unroll
        for (int t = 0; t < 2; t++) {
            int f4i = tid + t * 256;
            int wr = f4i >> 5, wc = (f4i & 31) * 4;
            *(uint4*)&Ws2[wr * WS_STRIDE + wc] =
                *(const uint4*)(Wp + (size_t)(kt * 16 + wr) * 128 + wc);
        }
        __syncthreads();
        mma_tile32(As2, Ws2, acc, lane, wm, wn);
        __syncthreads();
    }

    float csum[4][2] = {}, csq[4][2] = {};
#pragma unroll
    for (int mt = 0; mt < 4; mt++) {
        int r0 = m0 + wm * 64 + mt * 16 + (lane >> 2);
#pragma unroll
        for (int nt = 0; nt < 4; nt++) {
            int col = wn * 32 + nt * 8 + 2 * (lane & 3);
            float b0 = bias[col], b1 = bias[col + 1];
            float v0 = acc[mt][nt][0] + b0, v1 = acc[mt][nt][1] + b1;
            float v2 = acc[mt][nt][2] + b0, v3 = acc[mt][nt][3] + b1;
            if (r0 < NN) {
                *(float2*)(g_h2 + (size_t)r0 * 128 + col) = make_float2(v0, v1);
                csum[nt][0] += v0; csq[nt][0] += v0 * v0;
                csum[nt][1] += v1; csq[nt][1] += v1 * v1;
            }
            if (r0 + 8 < NN) {
                *(float2*)(g_h2 + (size_t)(r0 + 8) * 128 + col) = make_float2(v2, v3);
                csum[nt][0] += v2; csq[nt][0] += v2 * v2;
                csum[nt][1] += v3; csq[nt][1] += v3 * v3;
            }
        }
    }
#pragma unroll
    for (int nt = 0; nt < 4; nt++)
#pragma unroll
        for (int j = 0; j < 2; j++) {
            float s = csum[nt][j], q = csq[nt][j];
            s += __shfl_down_sync(0xffffffffu, s, 16);
            s += __shfl_down_sync(0xffffffffu, s, 8);
            s += __shfl_down_sync(0xffffffffu, s, 4);
            q += __shfl_down_sync(0xffffffffu, q, 16);
            q += __shfl_down_sync(0xffffffffu, q, 8);
            q += __shfl_down_sync(0xffffffffu, q, 4);
            if (lane < 4) {
                int col = wn * 32 + nt * 8 + 2 * lane + j;
                atomicAdd(&sbn[col], s);
                atomicAdd(&sbn[128 + col], q);
            }
        }
    __syncthreads();
    atomicAdd(&g_bn[tid], sbn[tid]);
}

// ---------------- fused edge message GEMM (fp16) + segmented aggregation ----------------
__global__ __launch_bounds__(256) void edge_agg(const unsigned* __restrict__ Wp,
                                                const float* __restrict__ biasm)
{
    extern __shared__ float s_dyn[];
    unsigned* su = (unsigned*)s_dyn;
    float* mt_ = s_dyn;                      // [128 x 132] fp32 m tile, reused
    __shared__ int sdst[128], ssrc[128], seid[128];

    int tid = threadIdx.x;
    int lane = tid & 31, warp = tid >> 5;
    int wm = warp >> 2, wn = warp & 3;
    int e0 = blockIdx.x * 128;
    int arow = tid >> 2;
    int slot = tid & 3;

    if (tid < 128) {
        int p = e0 + tid;
        sdst[tid] = g_pdst[p];
        ssrc[tid] = g_psrc[p];
        seid[tid] = g_peid[p];
    }
    __syncthreads();

    float acc[4][4][4];
#pragma unroll
    for (int a = 0; a < 4; a++)
#pragma unroll
        for (int b = 0; b < 4; b++)
#pragma unroll
            for (int c = 0; c < 4; c++) acc[a][b][c] = 0.f;

    auto a_sub = [&](int st, int j) { return su + st * 4096 + j * 2048; };
    auto w_sub = [&](int st, int j) { return su + 8192 + st * 4352 + j * 2176; };

    auto load_sub = [&](int kt, int st, int j) {   // kt in 0..8 (32-k tiles)
        unsigned* ab = a_sub(st, j);
        unsigned* wb = w_sub(st, j);
#pragma unroll
        for (int t = 0; t < 2; t++) {
            int r = arow + t * 64;
            const __half* src;
            if (kt < 4)      src = g_h16 + (size_t)sdst[r] * H + kt * 32 + slot * 8;
            else if (kt < 8) src = g_h16 + (size_t)ssrc[r] * H + (kt - 4) * 32 + slot * 8;
            else             src = g_ea16 + (size_t)seid[r] * 32 + slot * 8;
            cp16(&ab[r * 16 + ((slot ^ ((r >> 1) & 3)) << 2)], src);
        }
#pragma unroll
        for (int t = 0; t < 2; t++) {
            int f4i = tid + t * 256;
            int wr = f4i >> 5, wc = (f4i & 31) * 4;
            cp16(&wb[wr * WS_STRIDE + wc], Wp + (size_t)(kt * 16 + wr) * 128 + wc);
        }
    };

    load_sub(0, 0, 0); load_sub(1, 0, 1);
    CP_COMMIT();
    for (int p = 0; p < 5; p++) {            // 9 tiles as 4 pairs + 1
        if (p < 4) {
            int st = (p + 1) & 1;
            load_sub(2 * p + 2, st, 0);
            if (2 * p + 3 < 9) load_sub(2 * p + 3, st, 1);
            CP_COMMIT(); CP_WAIT1();
        } else CP_WAIT0();
        __syncthreads();
        int st = p & 1;
        mma_tile32(a_sub(st, 0), w_sub(st, 0), acc, lane, wm, wn);
        if (2 * p + 1 < 9)
            mma_tile32(a_sub(st, 1), w_sub(st, 1), acc, lane, wm, wn);
        __syncthreads();
    }

    // message tile (+bias) to SMEM (fp32)
#pragma unroll
    for (int mt2 = 0; mt2 < 4; mt2++) {
        int r0 = wm * 64 + mt2 * 16 + (lane >> 2);
#pragma unroll
        for (int nt = 0; nt < 4; nt++) {
            int col = wn * 32 + nt * 8 + 2 * (lane & 3);
            float b0 = biasm[col], b1 = biasm[col + 1];
            *(float2*)&mt_[r0 * 132 + col] =
                make_float2(acc[mt2][nt][0] + b0, acc[mt2][nt][1] + b1);
            *(float2*)&mt_[(r0 + 8) * 132 + col] =
                make_float2(acc[mt2][nt][2] + b0, acc[mt2][nt][3] + b1);
        }
    }
    __syncthreads();

    // segmented reduce: interior final (fp16 out), boundary via fp32 atomics
    int c = tid & 127, g2 = tid >> 7;
    int nfirst = sdst[0], nlast = sdst[127];
    for (int n = nfirst + g2; n <= nlast; n += 2) {
        int s = g_start[n], e = g_start[n + 1];
        if (s == e) continue;
        int lo = max(s, e0), hi = min(e, e0 + 128);
        if (lo >= hi) continue;
        float sumv = 0.f, sq = 0.f, mn = INFINITY, mx = -INFINITY;
        for (int r = lo - e0; r < hi - e0; r++) {
            float v = mt_[r * 132 + c];
            sumv += v; sq += v * v;
            mn = fminf(mn, v); mx = fmaxf(mx, v);
        }
        size_t idx = (size_t)n * H + c;
        if (s >= e0 && e <= e0 + 128) {
            float degc = (float)(e - s);
            float inv = 1.f / degc;
            float mean = sumv * inv;
            float var = fmaxf(sq * inv - mean * mean, 0.f);
            g_mean16[idx] = __float2half_rn(mean);
            g_std16[idx] = __float2half_rn(sqrtf(var + EPS_STD));
            g_mn16[idx] = __float2half_rn(mn);
            g_mx16[idx] = __float2half_rn(mx);
        } else {
            atomicAdd(&g_bsum[idx], sumv);
            atomicAdd(&g_bsq[idx], sq);
            atomicMinF(&g_bmn[idx], mn);
            atomicMaxF(&g_bmx[idx], mx);
        }
    }
}

// ---------------- boundary helpers ----------------
__global__ void bnd_build() {
    int n = blockIdx.x * blockDim.x + threadIdx.x;
    if (n >= NN) return;
    int s = g_start[n], e = g_start[n + 1];
    bool bnd = (s == e) || ((s >> 7) != ((e - 1) >> 7));
    if (bnd) {
        int p = atomicAdd(&g_bcnt, 1);
        g_blist[p] = n;
    }
}
__global__ void init_bnd() {
    int B = g_bcnt;
    int total = B * 128;
    for (int i = blockIdx.x * blockDim.x + threadIdx.x; i < total;
         i += gridDim.x * blockDim.x) {
        int n = g_blist[i >> 7];
        int c = i & 127;
        size_t idx = (size_t)n * H + c;
        g_bsum[idx] = 0.f; g_bsq[idx] = 0.f;
        g_bmn[idx] = INFINITY; g_bmx[idx] = -INFINITY;
    }
}
__global__ void fin_bnd() {
    int B = g_bcnt;
    int total = B * 128;
    for (int i = blockIdx.x * blockDim.x + threadIdx.x; i < total;
         i += gridDim.x * blockDim.x) {
        int n = g_blist[i >> 7];
        int c = i & 127;
        size_t idx = (size_t)n * H + c;
        int cnt = g_start[n + 1] - g_start[n];
        if (cnt == 0) {
            g_mean16[idx] = __float2half_rn(0.f);
            g_std16[idx] = __float2half_rn(sqrtf(EPS_STD));
            g_mn16[idx] = __float2half_rn(0.f);
            g_mx16[idx] = __float2half_rn(0.f);
        } else {
            float inv = 1.f / (float)cnt;
            float mean = g_bsum[idx] * inv;
            float var = fmaxf(g_bsq[idx] * inv - mean * mean, 0.f);
            g_mean16[idx] = __float2half_rn(mean);
            g_std16[idx] = __float2half_rn(sqrtf(var + EPS_STD));
            g_mn16[idx] = __float2half_rn(g_bmn[idx]);
            g_mx16[idx] = __float2half_rn(g_bmx[idx]);
        }
    }
}

// ---------------- post-NN gather-GEMM fp16 (52 tiles, reordered scaling) ----------------
__global__ __launch_bounds__(256) void post_gemmt(const unsigned* __restrict__ Wp,
                                                  const float* __restrict__ bias)
{
    extern __shared__ float s_dyn[];
    unsigned* su = (unsigned*)s_dyn;
    int tid = threadIdx.x;
    int lane = tid & 31, warp = tid >> 5;
    int wm = warp >> 2, wn = warp & 3;
    int n0 = blockIdx.x * 128;
    int arow = tid >> 2;
    int slot = tid & 3;

    float sa[8], si2[8];
#pragma unroll
    for (int mt = 0; mt < 4; mt++)
#pragma unroll
        for (int hh = 0; hh < 2; hh++) {
            int n = n0 + wm * 64 + mt * 16 + (lane >> 2) + hh * 8;
            if (n >= NN) n = NN - 1;
            float a = g_amp[n], ia = g_iamp[n];
            sa[mt * 2 + hh] = a;
            si2[mt * 2 + hh] = ia * ia;
        }

    float acc[4][4][4];
#pragma unroll
    for (int a = 0; a < 4; a++)
#pragma unroll
        for (int b = 0; b < 4; b++)
#pragma unroll
            for (int c = 0; c < 4; c++) acc[a][b][c] = 0.f;

    auto a_sub = [&](int st, int j) { return su + st * 4096 + j * 2048; };
    auto w_sub = [&](int st, int j) { return su + 8192 + st * 4352 + j * 2176; };

    auto load_sub = [&](int t, int st, int j) {
        int kt = map_t32(t);
        int b = kt >> 2;                     // 128-k block 0..12
        const __half* srcb;
        if (b == 0) srcb = g_h16;
        else {
            int a = (b - 1) & 3;
            srcb = (a == 0) ? g_mean16 : (a == 1) ? g_mn16 : (a == 2) ? g_mx16 : g_std16;
        }
        int kk0 = (kt & 3) * 32;
        unsigned* ab = a_sub(st, j);
        unsigned* wb = w_sub(st, j);
#pragma unroll
        for (int tt = 0; tt < 2; tt++) {
            int r = arow + tt * 64;
            int n = n0 + r;
            if (n >= NN) n = NN - 1;         // clamp (rows masked at epilogue)
            cp16(&ab[r * 16 + ((slot ^ ((r >> 1) & 3)) << 2)],
                 srcb + (size_t)n * H + kk0 + slot * 8);
        }
#pragma unroll
        for (int tt = 0; tt < 2; tt++) {
            int f4i = tid + tt * 256;
            int wr = f4i >> 5, wc = (f4i & 31) * 4;
            cp16(&wb[wr * WS_STRIDE + wc], Wp + (size_t)(kt * 16 + wr) * 128 + wc);
        }
    };

    load_sub(0, 0, 0); load_sub(1, 0, 1);
    CP_COMMIT();
    for (int p = 0; p < 26; p++) {           // 52 tiles as 26 pairs
        if (p < 25) {
            int st = (p + 1) & 1;
            load_sub(2 * p + 2, st, 0);
            load_sub(2 * p + 3, st, 1);
            CP_COMMIT(); CP_WAIT1();
        } else CP_WAIT0();
        __syncthreads();
        int st = p & 1;
        mma_tile32(a_sub(st, 0), w_sub(st, 0), acc, lane, wm, wn);
        mma_tile32(a_sub(st, 1), w_sub(st, 1), acc, lane, wm, wn);
        __syncthreads();
        if (p == 7) {            // U3 done -> * iamp^2
#pragma unroll
            for (int mt = 0; mt < 4; mt++)
#pragma unroll
                for (int nt = 0; nt < 4; nt++) {
                    acc[mt][nt][0] *= si2[mt * 2];     acc[mt][nt][1] *= si2[mt * 2];
                    acc[mt][nt][2] *= si2[mt * 2 + 1]; acc[mt][nt][3] *= si2[mt * 2 + 1];
                }
        } else if (p == 15) {    // U2 done -> * amp
#pragma unroll
            for (int mt = 0; mt < 4; mt++)
#pragma unroll
                for (int nt = 0; nt < 4; nt++) {
                    acc[mt][nt][0] *= sa[mt * 2];     acc[mt][nt][1] *= sa[mt * 2];
                    acc[mt][nt][2] *= sa[mt * 2 + 1]; acc[mt][nt][3] *= sa[mt * 2 + 1];
                }
        }
    }

#pragma unroll
    for (int mt = 0; mt < 4; mt++) {
        int r0 = n0 + wm * 64 + mt * 16 + (lane >> 2);
#pragma unroll
        for (int nt = 0; nt < 4; nt++) {
            int col = wn * 32 + nt * 8 + 2 * (lane & 3);
            float b0 = bias[col], b1 = bias[col + 1];
            if (r0 < NN)
                *(__half2*)(g_tmp16 + (size_t)r0 * 128 + col) =
                    __floats2half2_rn(acc[mt][nt][0] + b0, acc[mt][nt][1] + b1);
            if (r0 + 8 < NN)
                *(__half2*)(g_tmp16 + (size_t)(r0 + 8) * 128 + col) =
                    __floats2half2_rn(acc[mt][nt][2] + b0, acc[mt][nt][3] + b1);
        }
    }
}

// ---------------- packing / conversion ----------------
__global__ void pack_w(const float* __restrict__ W, unsigned* __restrict__ out,
                       int kpairs, int kmax) {
    int idx = blockIdx.x * blockDim.x + threadIdx.x;
    if (idx >= kpairs * 128) return;
    int kp = idx >> 7, n = idx & 127;
    float lo = (2 * kp < kmax) ? W[(size_t)(2 * kp) * 128 + n] : 0.f;
    float hi = (2 * kp + 1 < kmax) ? W[(size_t)(2 * kp + 1) * 128 + n] : 0.f;
    __half2 h = __floats2half2_rn(lo, hi);
    out[idx] = *(unsigned*)&h;
}
__global__ void ea_pack(const float* __restrict__ ea) {
    int idx = blockIdx.x * blockDim.x + threadIdx.x;
    if (idx >= NE * 32) return;
    int e = idx >> 5, j = idx & 31;
    g_ea16[idx] = __float2half_rn(j < 16 ? ea[(size_t)e * 16 + j] : 0.f);
}

// ---------------- sort / scan ----------------
__global__ void deg_count(const int* __restrict__ dstI) {
    int e = blockIdx.x * blockDim.x + threadIdx.x;
    if (e < NE) atomicAdd(&g_cnt[dstI[e]], 1);
}
__global__ __launch_bounds__(256) void scan1() {
    int b = blockIdx.x, t = threadIdx.x;
    int n = b * CHUNK + t;
    int v = (t < CHUNK && n < NN) ? g_cnt[n] : 0;
    int lane = t & 31, wid = t >> 5;
    int x = v;
#pragma unroll
    for (int off = 1; off < 32; off <<= 1) {
        int u = __shfl_up_sync(0xffffffffu, x, off);
        if (lane >= off) x += u;
    }
    __shared__ int wsum[8];
    if (lane == 31) wsum[wid] = x;
    __syncthreads();
    if (t == 0) {
        int r = 0;
#pragma unroll
        for (int i = 0; i < 8; i++) { int tmp = wsum[i]; wsum[i] = r; r += tmp; }
        g_part[b] = r;
    }
    __syncthreads();
    int excl = x - v + wsum[wid];
    if (t < CHUNK && n < NN) g_start[n] = excl;
}
__global__ void scan2() {
    int t = threadIdx.x;
    int v = g_part[t];
    int lane = t & 31, wid = t >> 5;
    int x = v;
#pragma unroll
    for (int off = 1; off < 32; off <<= 1) {
        int u = __shfl_up_sync(0xffffffffu, x, off);
        if (lane >= off) x += u;
    }
    __shared__ int wsum[4];
    if (lane == 31) wsum[wid] = x;
    __syncthreads();
    if (t == 0) {
        int r = 0;
#pragma unroll
        for (int i = 0; i < 4; i++) { int tmp = wsum[i]; wsum[i] = r; r += tmp; }
    }
    __syncthreads();
    g_part[t] = x - v + wsum[wid];
}
__global__ void scan3() {
    int n = blockIdx.x * blockDim.x + threadIdx.x;
    if (n < NN) {
        int s = g_start[n] + g_part[n / CHUNK];
        g_start[n] = s;
        g_cursor[n] = s;
    }
    if (n == 0) g_start[NN] = NE;
}
__global__ void scatter_k(const int* __restrict__ srcI, const int* __restrict__ dstI) {
    int e = blockIdx.x * blockDim.x + threadIdx.x;
    if (e >= NE) return;
    int d = dstI[e];
    int p = atomicAdd(&g_cursor[d], 1);
    g_psrc[p] = srcI[e];
    g_pdst[p] = d;
    g_peid[p] = e;
}
__global__ void amp_k() {
    int n = blockIdx.x * blockDim.x + threadIdx.x;
    if (n >= NN) return;
    float degc = fmaxf((float)g_cnt[n], 1.f);
    float a = logf(degc + 1.f) / AVG_LOG;
    g_amp[n] = a;
    g_iamp[n] = 1.f / a;
}
__global__ void biasm_k(const float* __restrict__ be, const float* __restrict__ eb,
                        const float* __restrict__ P2, float* __restrict__ out,
                        const float* __restrict__ pb) {
    int j = threadIdx.x;
    float s = pb[j];
    for (int k = 0; k < 16; k++)  s += be[k] * g_T1[k * H + j];
    for (int k = 0; k < H; k++)   s += eb[k] * P2[k * H + j];
    out[j] = s;
}

// ---------------- BN / pool / head ----------------
__global__ void bn_norm(const float* __restrict__ gamma, const float* __restrict__ beta) {
    int idx = blockIdx.x * blockDim.x + threadIdx.x;
    if (idx >= NN * H) return;
    int c = idx & 127;
    const float invN = 1.f / (float)NN;
    float mu = g_bn[c] * invN;
    float var = g_bn[128 + c] * invN - mu * mu;
    float y = (g_h2[idx] - mu) * rsqrtf(var + EPS_BN) * gamma[c] + beta[c];
    y = fmaxf(y, 0.f);
    g_h[idx] = y;
    g_h16[idx] = __float2half_rn(y);
}
__global__ void pool_k(const int* __restrict__ batch) {
    int c = threadIdx.x;
    int start = blockIdx.x * 256;
    int end = min(start + 256, NN);
    if (start >= NN) return;
    float acc = 0.f;
    int cur = batch[start];
    for (int n = start; n < end; n++) {
        int g = batch[n];
        if (g != cur) { atomicAdd(&g_pool[cur * H + c], acc); acc = 0.f; cur = g; }
        acc += g_h[(size_t)n * H + c];
    }
    atomicAdd(&g_pool[cur * H + c], acc);
}
__global__ void head1_k(const float* __restrict__ W1, const float* __restrict__ b1) {
    int idx = blockIdx.x * blockDim.x + threadIdx.x;
    if (idx >= NGR * 64) return;
    int g = idx >> 6, j = idx & 63;
    float s = b1[j];
    for (int k = 0; k < H; k++) s += g_pool[g * H + k] * W1[k * 64 + j];
    g_z[idx] = fmaxf(s, 0.f);
}
__global__ void head2_k(const float* __restrict__ W2, const float* __restrict__ b2,
                        float* __restrict__ out) {
    int idx = blockIdx.x * blockDim.x + threadIdx.x;
    if (idx >= NGR * NOUT) return;
    int g = idx / NOUT, j = idx % NOUT;
    float s = b2[j];
    for (int k = 0; k < 64; k++) s += g_z[g * 64 + k] * W2[k * NOUT + j];
    out[idx] = s;
}

// ---------------- launch ----------------
extern "C" void kernel_launch(void* const* d_in, const int* in_sizes, int n_in,
                              void* d_out, int out_size)
{
    int iEI = 1, iBatch = 2, iEA = 3;
    if (in_sizes[1] == NE * 16) { iEA = 1; iEI = 2; iBatch = 3; }

    const float* x         = (const float*)d_in[0];
    const int*   edge_index= (const int*)  d_in[iEI];
    const int*   batch     = (const int*)  d_in[iBatch];
    const float* edge_attr = (const float*)d_in[iEA];
    const float* node_emb_W= (const float*)d_in[4];
    const float* node_emb_b= (const float*)d_in[5];
    const float* edge_emb_W= (const float*)d_in[6];
    const float* edge_emb_b= (const float*)d_in[7];
    const float* edge_enc_W= (const float*)d_in[8];
    const float* edge_enc_b= (const float*)d_in[9];
    const float* pre_W     = (const float*)d_in[10];
    const float* pre_b     = (const float*)d_in[11];
    const float* post_W    = (const float*)d_in[12];
    const float* post_b    = (const float*)d_in[13];
    const float* lin_W     = (const float*)d_in[14];
    const float* lin_b     = (const float*)d_in[15];
    const float* bn_gamma  = (const float*)d_in[16];
    const float* bn_beta   = (const float*)d_in[17];
    const float* head1_W   = (const float*)d_in[18];
    const float* head1_b   = (const float*)d_in[19];
    const float* head2_W   = (const float*)d_in[20];
    const float* head2_b   = (const float*)d_in[21];

    const int* srcI = edge_index;
    const int* dstI = edge_index + NE;

    float *p_wcat, *p_T1, *p_biasm, *p_bn, *p_pool;
    unsigned *p_wcatH, *p_postWH, *p_linWH;
    int *p_cnt, *p_bcnt;
    cudaGetSymbolAddress((void**)&p_wcat,   g_WcatL);
    cudaGetSymbolAddress((void**)&p_wcatH,  g_WcatH);
    cudaGetSymbolAddress((void**)&p_postWH, g_postWH);
    cudaGetSymbolAddress((void**)&p_linWH,  g_linWH);
    cudaGetSymbolAddress((void**)&p_T1,     g_T1);
    cudaGetSymbolAddress((void**)&p_biasm,  g_biasmL);
    cudaGetSymbolAddress((void**)&p_bn,     g_bn);
    cudaGetSymbolAddress((void**)&p_pool,   g_pool);
    cudaGetSymbolAddress((void**)&p_cnt,    g_cnt);
    cudaGetSymbolAddress((void**)&p_bcnt,   g_bcnt);

    cudaFuncSetAttribute(edge_agg, cudaFuncAttributeMaxDynamicSharedMemorySize, BIG_SMEM);
    cudaFuncSetAttribute(post_gemmt, cudaFuncAttributeMaxDynamicSharedMemorySize, BIG_SMEM);

    // sort prep
    cudaMemsetAsync(p_cnt, 0, NN * sizeof(int));
    cudaMemsetAsync(p_bcnt, 0, sizeof(int));
    deg_count<<<(NE + 255) / 256, 256>>>(dstI);
    scan1<<<SCAN_B, 256>>>();
    scan2<<<1, 128>>>();
    emb_gemmt<<<(NN + 127) / 128, 256>>>(x, node_emb_W, node_emb_b, 64);
    scan3<<<(NN + 255) / 256, 256>>>();
    scatter_k<<<(NE + 255) / 256, 256>>>(srcI, dstI);
    amp_k<<<(NN + 255) / 256, 256>>>();
    bnd_build<<<(NN + 255) / 256, 256>>>();
    ea_pack<<<(NE * 32 + 255) / 256, 256>>>(edge_attr);

    // weight prep + fp16 packing
    for (int l = 0; l < NL; l++) {
        const float* preWl = pre_W + (size_t)l * 384 * H;
        const float* P2 = preWl + 256 * H;
        float* wcat_l = p_wcat + (size_t)l * KCAT * H;
        cudaMemcpyAsync(wcat_l, preWl, 256 * H * sizeof(float), cudaMemcpyDeviceToDevice);
        gemm128<<<1, 256>>>(edge_enc_W + (size_t)l * H * H, P2,
                            (const float*)nullptr, p_T1, 128, 128);
        gemm128<<<1, 256>>>(edge_emb_W, p_T1,
                            (const float*)nullptr, wcat_l + 256 * H, 16, 128);
        biasm_k<<<1, 128>>>(edge_emb_b, edge_enc_b + l * H, P2,
                            p_biasm + l * H, pre_b + l * H);
        pack_w<<<(KP_EDGE * 128 + 255) / 256, 256>>>(
            wcat_l, p_wcatH + (size_t)l * KP_EDGE * H, KP_EDGE, KCAT);
        pack_w<<<(KP_POST * 128 + 255) / 256, 256>>>(
            post_W + (size_t)l * 13 * H * H, p_postWH + (size_t)l * KP_POST * H,
            KP_POST, 13 * H);
        pack_w<<<(KP_LIN * 128 + 255) / 256, 256>>>(
            lin_W + (size_t)l * H * H, p_linWH + (size_t)l * KP_LIN * H,
            KP_LIN, H);
    }

    for (int l = 0; l < NL; l++) {
        init_bnd<<<64, 256>>>();
        edge_agg<<<NE / 128, 256, BIG_SMEM>>>(p_wcatH + (size_t)l * KP_EDGE * H,
                                              p_biasm + l * H);
        fin_bnd<<<64, 256>>>();

        post_gemmt<<<(NN + 127) / 128, 256, BIG_SMEM>>>(
            p_postWH + (size_t)l * KP_POST * H, post_b + l * H);

        cudaMemsetAsync(p_bn, 0, 2 * H * sizeof(float));
        lin_gemm_bn<<<(NN + 127) / 128, 256>>>(p_linWH + (size_t)l * KP_LIN * H,
                                               lin_b + l * H);
        bn_norm<<<(NN * H + 255) / 256, 256>>>(bn_gamma + l * H, bn_beta + l * H);
    }

    cudaMemsetAsync(p_pool, 0, NGR * H * sizeof(float));
    pool_k<<<(NN + 255) / 256, 128>>>(batch);
    head1_k<<<8, 256>>>(head1_W, head1_b);
    head2_k<<<2, 256>>>(head2_W, head2_b, (float*)d_out);
}